// round 8
// baseline (speedup 1.0000x reference)
#include <cuda_runtime.h>
#include <cuda_fp16.h>
#include <math.h>
#include <stdint.h>

#define B_    4
#define NTOK  16384
#define C_    256
#define BN_   65536
#define NSPL  8                  // inpgram K-splits

// ---------------- static device scratch ----------------
__device__ __half g_v[BN_ * C_];                 // 32 MB
__device__ __half g_Wt[3 * C_ * C_];             // fp16 transposed weights [N][K]
__device__ __half g_Mt[B_ * C_ * C_];            // fp16 transposed fused attn*Wp
__device__ float g_gpart[12 * 2 * NSPL * 128 * 256];   // 24 MB input-gram partials
__device__ float g_S[12 * C_ * C_];              // S1,S2,T3 per batch (3 MB)
__device__ float g_P[12 * C_ * C_];              // P1,P2,U3 per batch (3 MB)

__device__ __forceinline__ void mma_f16(float* c, const uint32_t* a, const uint32_t* b) {
    asm volatile(
        "mma.sync.aligned.m16n8k16.row.col.f32.f16.f16.f32 "
        "{%0,%1,%2,%3}, {%4,%5,%6,%7}, {%8,%9}, {%0,%1,%2,%3};"
        : "+f"(c[0]), "+f"(c[1]), "+f"(c[2]), "+f"(c[3])
        : "r"(a[0]), "r"(a[1]), "r"(a[2]), "r"(a[3]), "r"(b[0]), "r"(b[1]));
}
__device__ __forceinline__ void cp16(void* s, const void* g) {
    uint32_t sa = (uint32_t)__cvta_generic_to_shared(s);
    asm volatile("cp.async.cg.shared.global [%0], [%1], 16;" :: "r"(sa), "l"(g));
}
#define CP_COMMIT() asm volatile("cp.async.commit_group;" ::: "memory")
#define CP_WAIT0()  asm volatile("cp.async.wait_group 0;" ::: "memory")

__device__ __forceinline__ void ldsm4t(uint32_t* r, const __half* p) {
    uint32_t a = (uint32_t)__cvta_generic_to_shared(p);
    asm volatile("ldmatrix.sync.aligned.m8n8.x4.trans.shared.b16 {%0,%1,%2,%3}, [%4];"
                 : "=r"(r[0]), "=r"(r[1]), "=r"(r[2]), "=r"(r[3]) : "r"(a));
}
__device__ __forceinline__ void ldsm2t(uint32_t* r, const __half* p) {
    uint32_t a = (uint32_t)__cvta_generic_to_shared(p);
    asm volatile("ldmatrix.sync.aligned.m8n8.x2.trans.shared.b16 {%0,%1}, [%2];"
                 : "=r"(r[0]), "=r"(r[1]) : "r"(a));
}

// =================== input grams: S1=XtX, S2=YtY, T3=YtX (fp16 mma, split-K) ===================
// grid (NSPL, 2 m-half, 12 pb), 512 thr. Block out: 128x256 fp32 partial, K=2048 tokens.
#define RS 264      // smem row stride in halves (256 + 8) -> conflict-free ldmatrix

__global__ void __launch_bounds__(512) k_inpgram(
    const float* __restrict__ x, const float* __restrict__ y)
{
    __shared__ __half sA[2][16 * RS];
    __shared__ __half sB[2][16 * RS];

    const int s = blockIdx.x, half = blockIdx.y, pb = blockIdx.z;
    const int p = pb >> 2, b = pb & 3;
    const float* Ag = (p == 0) ? x : y;        // M-operand tensor
    const float* Bg = (p == 1) ? y : x;        // N-operand tensor
    const bool dual = (p == 2);
    const size_t base = ((size_t)b * NTOK + (size_t)s * 2048) * 256;

    const int t = threadIdx.x, warp = t >> 5, lane = t & 31;
    const int wm = (warp & 1) * 64;            // within the 128-row half
    const int wn = (warp >> 1) * 32;
    // ldmatrix lane row/col offsets
    const int lrowA = (lane & 7) + ((lane >> 4) << 3);
    const int lcolA = ((lane >> 3) & 1) << 3;
    const int lrowB = (lane & 7) + (((lane >> 3) & 1) << 3);

    float acc[4][4][4];
#pragma unroll
    for (int mf = 0; mf < 4; mf++)
#pragma unroll
        for (int nf = 0; nf < 4; nf++)
#pragma unroll
            for (int r = 0; r < 4; r++) acc[mf][nf][r] = 0.f;

    // staging: chunk = 16 tok x 256 ch fp32 per operand; thread does 2 float4 per operand
    const int u0 = t, u1 = t + 512;
    const int tok0 = u0 >> 6, c40 = (u0 & 63) * 4;
    const int tok1 = u1 >> 6, c41 = (u1 & 63) * 4;

    float4 ra0, ra1, rb0, rb1;
    // prologue: chunk 0
    ra0 = *(const float4*)(Ag + base + (size_t)tok0 * 256 + c40);
    ra1 = *(const float4*)(Ag + base + (size_t)tok1 * 256 + c41);
    if (dual) {
        rb0 = *(const float4*)(Bg + base + (size_t)tok0 * 256 + c40);
        rb1 = *(const float4*)(Bg + base + (size_t)tok1 * 256 + c41);
    }
    {
        __half2 h[2];
        h[0] = __float22half2_rn(make_float2(ra0.x, ra0.y));
        h[1] = __float22half2_rn(make_float2(ra0.z, ra0.w));
        *(uint2*)&sA[0][tok0 * RS + c40] = *(const uint2*)h;
        h[0] = __float22half2_rn(make_float2(ra1.x, ra1.y));
        h[1] = __float22half2_rn(make_float2(ra1.z, ra1.w));
        *(uint2*)&sA[0][tok1 * RS + c41] = *(const uint2*)h;
        if (dual) {
            h[0] = __float22half2_rn(make_float2(rb0.x, rb0.y));
            h[1] = __float22half2_rn(make_float2(rb0.z, rb0.w));
            *(uint2*)&sB[0][tok0 * RS + c40] = *(const uint2*)h;
            h[0] = __float22half2_rn(make_float2(rb1.x, rb1.y));
            h[1] = __float22half2_rn(make_float2(rb1.z, rb1.w));
            *(uint2*)&sB[0][tok1 * RS + c41] = *(const uint2*)h;
        }
    }
    __syncthreads();

    for (int c = 0; c < 128; c++) {
        const int st = c & 1;
        if (c < 127) {
            const size_t off = base + (size_t)(c + 1) * 16 * 256;
            ra0 = *(const float4*)(Ag + off + (size_t)tok0 * 256 + c40);
            ra1 = *(const float4*)(Ag + off + (size_t)tok1 * 256 + c41);
            if (dual) {
                rb0 = *(const float4*)(Bg + off + (size_t)tok0 * 256 + c40);
                rb1 = *(const float4*)(Bg + off + (size_t)tok1 * 256 + c41);
            }
        }
        // compute chunk c
        const __half* bufA = sA[st];
        const __half* bufB = dual ? sB[st] : sA[st];
        uint32_t bf[4][2];
#pragma unroll
        for (int nf = 0; nf < 4; nf++)
            ldsm2t(bf[nf], &bufB[lrowB * RS + wn + nf * 8]);
#pragma unroll
        for (int mf = 0; mf < 4; mf++) {
            uint32_t af[4];
            ldsm4t(af, &bufA[lrowA * RS + half * 128 + wm + mf * 16 + lcolA]);
#pragma unroll
            for (int nf = 0; nf < 4; nf++)
                mma_f16(acc[mf][nf], af, bf[nf]);
        }
        __syncthreads();
        if (c < 127) {
            const int ns = st ^ 1;
            __half2 h[2];
            h[0] = __float22half2_rn(make_float2(ra0.x, ra0.y));
            h[1] = __float22half2_rn(make_float2(ra0.z, ra0.w));
            *(uint2*)&sA[ns][tok0 * RS + c40] = *(const uint2*)h;
            h[0] = __float22half2_rn(make_float2(ra1.x, ra1.y));
            h[1] = __float22half2_rn(make_float2(ra1.z, ra1.w));
            *(uint2*)&sA[ns][tok1 * RS + c41] = *(const uint2*)h;
            if (dual) {
                h[0] = __float22half2_rn(make_float2(rb0.x, rb0.y));
                h[1] = __float22half2_rn(make_float2(rb0.z, rb0.w));
                *(uint2*)&sB[ns][tok0 * RS + c40] = *(const uint2*)h;
                h[0] = __float22half2_rn(make_float2(rb1.x, rb1.y));
                h[1] = __float22half2_rn(make_float2(rb1.z, rb1.w));
                *(uint2*)&sB[ns][tok1 * RS + c41] = *(const uint2*)h;
            }
            __syncthreads();
        }
    }

    // write 128x256 fp32 partial
    float* out = g_gpart + ((size_t)(pb * 2 + half) * NSPL + s) * 32768;
    const int g = lane >> 2, q = lane & 3;
#pragma unroll
    for (int mf = 0; mf < 4; mf++) {
        int i = wm + mf * 16 + g;
#pragma unroll
        for (int nf = 0; nf < 4; nf++) {
            int j = wn + nf * 8 + 2 * q;
            *(float2*)(out + (size_t)i * 256 + j) = make_float2(acc[mf][nf][0], acc[mf][nf][1]);
            *(float2*)(out + (size_t)(i + 8) * 256 + j) = make_float2(acc[mf][nf][2], acc[mf][nf][3]);
        }
    }
}

// reduce split partials -> g_S.  grid (256, 12), 256 thr
__global__ void k_sred()
{
    int pb = blockIdx.y;
    int e = blockIdx.x * 256 + threadIdx.x;   // 0..65535
    int i = e >> 8, j = e & 255;
    int half = i >> 7, il = i & 127;
    const float* src = g_gpart + ((size_t)(pb * 2 + half) * NSPL) * 32768 + (size_t)il * 256 + j;
    float acc = 0.f;
#pragma unroll
    for (int s = 0; s < NSPL; s++) acc += src[(size_t)s * 32768];
    g_S[(size_t)pb * 65536 + e] = acc;
}

// =================== shared 128x256 GEMM: C = A(fp32->fp16) x Bt^T ===================
// 512 thr = 16 warps (2m x 8n), K=256, chunk 16, 2-stage cp.async for B.
#define KC   16
#define SPH  24

template <bool OUTH>
__device__ __forceinline__ void gemm_f32a(
    const float* __restrict__ A, const __half* __restrict__ Bt,
    void* __restrict__ Cv, int row0)
{
    __shared__ __half As[2][128 * SPH];
    __shared__ __half Bs[2][256 * SPH];

    const int t = threadIdx.x;
    const int warp = t >> 5, lane = t & 31;
    const int wm0 = (warp & 1) * 64;
    const int wn0 = (warp >> 1) * 32;
    const int g = lane >> 2;
    const int q = lane & 3;

    float acc[4][4][4];
#pragma unroll
    for (int mf = 0; mf < 4; mf++)
#pragma unroll
        for (int nf = 0; nf < 4; nf++)
#pragma unroll
            for (int r = 0; r < 4; r++) acc[mf][nf][r] = 0.f;

    const int ar = t >> 2, ak = (t & 3) * 4;
    const float* Ab = A + (size_t)(row0 + ar) * 256 + ak;
    const int br = t >> 1, bk = (t & 1) * 8;
    const __half* Bb = Bt + (size_t)br * 256 + bk;

    {
        float4 pa = *(const float4*)(Ab);
        cp16(&Bs[0][br * SPH + bk], Bb);
        CP_COMMIT();
        __half2 h[2];
        h[0] = __float22half2_rn(make_float2(pa.x, pa.y));
        h[1] = __float22half2_rn(make_float2(pa.z, pa.w));
        *(uint2*)&As[0][ar * SPH + ak] = *(const uint2*)h;
    }

    for (int c = 0; c < 16; c++) {
        const int st = c & 1;
        CP_WAIT0();
        __syncthreads();
        if (c < 15) {
            const int k0 = (c + 1) * KC;
            float4 pa = *(const float4*)(Ab + k0);
            cp16(&Bs[st ^ 1][br * SPH + bk], Bb + k0);
            CP_COMMIT();
            __half2 h[2];
            h[0] = __float22half2_rn(make_float2(pa.x, pa.y));
            h[1] = __float22half2_rn(make_float2(pa.z, pa.w));
            *(uint2*)&As[st ^ 1][ar * SPH + ak] = *(const uint2*)h;
        }
        uint32_t bf[4][2];
#pragma unroll
        for (int nf = 0; nf < 4; nf++) {
            int n = wn0 + nf * 8 + g;
            bf[nf][0] = *(const uint32_t*)&Bs[st][n * SPH + 2 * q];
            bf[nf][1] = *(const uint32_t*)&Bs[st][n * SPH + 2 * q + 8];
        }
#pragma unroll
        for (int mf = 0; mf < 4; mf++) {
            int r = wm0 + mf * 16 + g;
            uint32_t af[4];
            af[0] = *(const uint32_t*)&As[st][r * SPH + 2 * q];
            af[1] = *(const uint32_t*)&As[st][(r + 8) * SPH + 2 * q];
            af[2] = *(const uint32_t*)&As[st][r * SPH + 2 * q + 8];
            af[3] = *(const uint32_t*)&As[st][(r + 8) * SPH + 2 * q + 8];
#pragma unroll
            for (int nf = 0; nf < 4; nf++)
                mma_f16(acc[mf][nf], af, bf[nf]);
        }
    }

#pragma unroll
    for (int mf = 0; mf < 4; mf++) {
        int rbase = row0 + wm0 + mf * 16 + g;
#pragma unroll
        for (int nf = 0; nf < 4; nf++) {
            int cb = wn0 + nf * 8 + 2 * q;
            if (OUTH) {
                __half* C = (__half*)Cv;
                *(__half2*)(C + (size_t)rbase * 256 + cb)
                    = __float22half2_rn(make_float2(acc[mf][nf][0], acc[mf][nf][1]));
                *(__half2*)(C + (size_t)(rbase + 8) * 256 + cb)
                    = __float22half2_rn(make_float2(acc[mf][nf][2], acc[mf][nf][3]));
            } else {
                float* C = (float*)Cv;
                *(float2*)(C + (size_t)rbase * 256 + cb)
                    = make_float2(acc[mf][nf][0], acc[mf][nf][1]);
                *(float2*)(C + (size_t)(rbase + 8) * 256 + cb)
                    = make_float2(acc[mf][nf][2], acc[mf][nf][3]);
            }
        }
    }
}

// v = f @ Wv  (fp16 out), grid 512
__global__ void __launch_bounds__(512) k_gemm_v(const float* __restrict__ f)
{
    gemm_f32a<true>(f, g_Wt + 2 * 65536, g_v, blockIdx.x * 128);
}

// P1=S1*Wq, P2=S2*Wk, U3=T3*Wq  (fp32 out), grid (2, 12)
__global__ void __launch_bounds__(512) k_mm2()
{
    int pb = blockIdx.y;
    int p = pb >> 2;
    int sel = (p == 1) ? 1 : 0;
    gemm_f32a<false>(g_S + (size_t)pb * 65536, g_Wt + (size_t)sel * 65536,
                     g_P + (size_t)pb * 65536, blockIdx.x * 128);
}

// ---- OUT: A fp16 (g_v) + B fp16 (g_Mt), accumulate into f32 d_out + bias ----
__global__ void __launch_bounds__(512) k_gemm_out(
    const float* __restrict__ bp, float* __restrict__ out)
{
    __shared__ __half As[2][128 * SPH];
    __shared__ __half Bs[2][256 * SPH];

    const int row0 = blockIdx.x * 128;
    const int b = row0 >> 14;
    const __half* Ab0 = g_v;
    const __half* Bt = g_Mt + (size_t)b * 65536;

    const int t = threadIdx.x;
    const int warp = t >> 5, lane = t & 31;
    const int wm0 = (warp & 1) * 64;
    const int wn0 = (warp >> 1) * 32;
    const int g = lane >> 2;
    const int q = lane & 3;

    float acc[4][4][4];
#pragma unroll
    for (int mf = 0; mf < 4; mf++)
#pragma unroll
        for (int nf = 0; nf < 4; nf++)
#pragma unroll
            for (int r = 0; r < 4; r++) acc[mf][nf][r] = 0.f;

    const int ar = t >> 1, ak = (t & 1) * 8;
    const __half* Ab = Ab0 + (size_t)(row0 + ar) * 256 + ak;
    const __half* Bb = Bt + (size_t)ar * 256 + ak;

    if (t < 256) cp16(&As[0][ar * SPH + ak], Ab);
    cp16(&Bs[0][ar * SPH + ak], Bb);
    CP_COMMIT();

    for (int c = 0; c < 16; c++) {
        const int st = c & 1;
        CP_WAIT0();
        __syncthreads();
        if (c < 15) {
            const int k0 = (c + 1) * KC;
            if (t < 256) cp16(&As[st ^ 1][ar * SPH + ak], Ab + k0);
            cp16(&Bs[st ^ 1][ar * SPH + ak], Bb + k0);
            CP_COMMIT();
        }
        uint32_t bf[4][2];
#pragma unroll
        for (int nf = 0; nf < 4; nf++) {
            int n = wn0 + nf * 8 + g;
            bf[nf][0] = *(const uint32_t*)&Bs[st][n * SPH + 2 * q];
            bf[nf][1] = *(const uint32_t*)&Bs[st][n * SPH + 2 * q + 8];
        }
#pragma unroll
        for (int mf = 0; mf < 4; mf++) {
            int r = wm0 + mf * 16 + g;
            uint32_t af[4];
            af[0] = *(const uint32_t*)&As[st][r * SPH + 2 * q];
            af[1] = *(const uint32_t*)&As[st][(r + 8) * SPH + 2 * q];
            af[2] = *(const uint32_t*)&As[st][r * SPH + 2 * q + 8];
            af[3] = *(const uint32_t*)&As[st][(r + 8) * SPH + 2 * q + 8];
#pragma unroll
            for (int nf = 0; nf < 4; nf++)
                mma_f16(acc[mf][nf], af, bf[nf]);
        }
    }

#pragma unroll
    for (int mf = 0; mf < 4; mf++) {
        int rbase = row0 + wm0 + mf * 16 + g;
#pragma unroll
        for (int nf = 0; nf < 4; nf++) {
            int cb = wn0 + nf * 8 + 2 * q;
            float2 bb = *(const float2*)(bp + cb);
            float2* p0 = (float2*)(out + (size_t)rbase * 256 + cb);
            float2* p1 = (float2*)(out + (size_t)(rbase + 8) * 256 + cb);
            float2 o0 = *p0, o1 = *p1;
            o0.x += acc[mf][nf][0] + bb.x; o0.y += acc[mf][nf][1] + bb.y;
            o1.x += acc[mf][nf][2] + bb.x; o1.y += acc[mf][nf][3] + bb.y;
            *p0 = o0;
            *p1 = o1;
        }
    }
}

// =================== weight transpose + fp16 conversion ===================
__global__ void k_wt(const float* __restrict__ Wq, const float* __restrict__ Wk,
                     const float* __restrict__ Wv)
{
    int z = blockIdx.z;
    const float* W = (z == 0) ? Wq : (z == 1) ? Wk : Wv;
    __half* Wt = g_Wt + (size_t)z * 65536;
    __shared__ float tile[32][33];
    int tx = threadIdx.x, ty = threadIdx.y;
    int k0 = blockIdx.y * 32, n0 = blockIdx.x * 32;
#pragma unroll
    for (int i = 0; i < 4; i++)
        tile[ty + 8 * i][tx] = W[(size_t)(k0 + ty + 8 * i) * 256 + n0 + tx];
    __syncthreads();
#pragma unroll
    for (int i = 0; i < 4; i++)
        Wt[(size_t)(n0 + ty + 8 * i) * 256 + k0 + tx] = __float2half_rn(tile[tx][ty + 8 * i]);
}

// =================== norms + G + softmax + fold into Wp -> Mt ===================
// grid (32 bh), 256 thr
__global__ void __launch_bounds__(256) k_attn_m(
    const float* __restrict__ Wq, const float* __restrict__ Wk,
    const float* __restrict__ Wp, const float* __restrict__ rescale)
{
    int bh = blockIdx.x, b = bh >> 3, h = bh & 7;
    int t = threadIdx.x;
    int j = t & 31, ig = t >> 5;
    __shared__ float wks[256][33];
    __shared__ float attn[32][32];
    __shared__ float nq[32], nk[32];
    __shared__ float redq[8][32], redk[8][32];

    // norms: nq_j^2 = sum_a Wq[a][hj] * P1[b][a][hj]
    {
        int col = h * 32 + j;
        const float* P1 = g_P + (size_t)(0 * 4 + b) * 65536;
        const float* P2 = g_P + (size_t)(1 * 4 + b) * 65536;
        float pq = 0.f, pk = 0.f;
        for (int a = ig; a < 256; a += 8) {
            pq += Wq[(size_t)a * 256 + col] * P1[(size_t)a * 256 + col];
            pk += Wk[(size_t)a * 256 + col] * P2[(size_t)a * 256 + col];
        }
        redq[ig][j] = pq; redk[ig][j] = pk;
    }
    // wks[a][i] = Wk[a][h*32+i]
    for (int idx = t; idx < 8192; idx += 256) {
        int a = idx >> 5, i = idx & 31;
        wks[a][i] = Wk[(size_t)a * 256 + h * 32 + i];
    }
    __syncthreads();
    if (t < 32) {
        float aq = 0.f, ak = 0.f;
#pragma unroll
        for (int r = 0; r < 8; r++) { aq += redq[r][t]; ak += redk[r][t]; }
        nq[t] = fmaxf(sqrtf(aq), 1e-12f);
        nk[t] = fmaxf(sqrtf(ak), 1e-12f);
    }
    __syncthreads();

    // G[i][j] = sum_a Wk[a][h32+i] * U3[b][a][h32+j]
    float ga[4] = {0.f, 0.f, 0.f, 0.f};
    {
        const float* U3 = g_P + (size_t)(2 * 4 + b) * 65536 + h * 32 + j;
        for (int a = 0; a < 256; a++) {
            float u = U3[(size_t)a * 256];
#pragma unroll
            for (int sidx = 0; sidx < 4; sidx++)
                ga[sidx] += wks[a][ig + 8 * sidx] * u;
        }
    }
    float resc = rescale[h];
#pragma unroll
    for (int sidx = 0; sidx < 4; sidx++) {
        int i = ig + 8 * sidx;
        float val = ga[sidx] / (nk[i] * nq[j]) * resc;
        float m = val;
#pragma unroll
        for (int o = 16; o; o >>= 1) m = fmaxf(m, __shfl_xor_sync(0xffffffffu, m, o));
        float e = expf(val - m);
        float ssum = e;
#pragma unroll
        for (int o = 16; o; o >>= 1) ssum += __shfl_xor_sync(0xffffffffu, ssum, o);
        attn[i][j] = e / ssum;
    }
    __syncthreads();

    // Mt[b][c=t][h*32+jj] = sum_i attn[i][jj] * Wp[h*32+i][c]
    float acc[32];
#pragma unroll
    for (int jj = 0; jj < 32; jj++) acc[jj] = 0.f;
#pragma unroll 4
    for (int i = 0; i < 32; i++) {
        float wpv = Wp[(size_t)(h * 32 + i) * 256 + t];
#pragma unroll
        for (int jj = 0; jj < 32; jj++) acc[jj] += attn[i][jj] * wpv;
    }
#pragma unroll
    for (int jj = 0; jj < 32; jj++)
        g_Mt[((size_t)b * 256 + t) * 256 + h * 32 + jj] = __float2half_rn(acc[jj]);
}

// =================== fused positional branch (reads fp16 v) ===================
__device__ __forceinline__ float gelu_exact(float x)
{
    return 0.5f * x * (1.0f + erff(x * 0.7071067811865475f));
}

__global__ void __launch_bounds__(256) k_conv(
    const float* __restrict__ pw1, const float* __restrict__ pw2,
    float* __restrict__ out)
{
    __shared__ float vs[20][20][16];
    __shared__ float t1[18][18][16];
    const int t = threadIdx.x;
    const int cl = t & 15;
    const int tp = t >> 4;
    const int c = (blockIdx.y << 4) + cl;
    const int tx0 = (blockIdx.x & 7) * 16, ty0 = (blockIdx.x >> 3) * 16;
    const int b = blockIdx.z;

    float w1[9], w2[9];
#pragma unroll
    for (int i = 0; i < 9; i++) {
        w1[i] = pw1[i * 256 + c];
        w2[i] = pw2[i * 256 + c];
    }

    for (int p = tp; p < 400; p += 16) {
        int py = p / 20, px = p - py * 20;
        int gy = ty0 + py - 2, gx = tx0 + px - 2;
        float v = 0.f;
        if (gy >= 0 && gy < 128 && gx >= 0 && gx < 128)
            v = __half2float(g_v[(((size_t)(b * 128 + gy)) * 128 + gx) * 256 + c]);
        vs[py][px][cl] = v;
    }
    __syncthreads();

    for (int p = tp; p < 324; p += 16) {
        int py = p / 18, px = p - py * 18;
        float acc = 0.f;
#pragma unroll
        for (int dy = 0; dy < 3; dy++)
#pragma unroll
            for (int dx = 0; dx < 3; dx++)
                acc += vs[py + dy][px + dx][cl] * w1[dy * 3 + dx];
        int gy = ty0 + py - 1, gx = tx0 + px - 1;
        float val = (gy >= 0 && gy < 128 && gx >= 0 && gx < 128) ? gelu_exact(acc) : 0.f;
        t1[py][px][cl] = val;
    }
    __syncthreads();

    for (int p = tp; p < 256; p += 16) {
        int py = p >> 4, px = p & 15;
        float acc = 0.f;
#pragma unroll
        for (int dy = 0; dy < 3; dy++)
#pragma unroll
            for (int dx = 0; dx < 3; dx++)
                acc += t1[py + dy][px + dx][cl] * w2[dy * 3 + dx];
        out[(((size_t)(b * 128 + ty0 + py)) * 128 + tx0 + px) * 256 + c] = acc;
    }
}

extern "C" void kernel_launch(void* const* d_in, const int* in_sizes, int n_in,
                              void* d_out, int out_size)
{
    const float* x_in    = (const float*)d_in[0];
    const float* y_in    = (const float*)d_in[1];
    const float* f_in    = (const float*)d_in[2];
    const float* Wq      = (const float*)d_in[3];
    const float* Wk      = (const float*)d_in[4];
    const float* Wv      = (const float*)d_in[5];
    const float* rescale = (const float*)d_in[6];
    const float* Wp      = (const float*)d_in[7];
    const float* bp      = (const float*)d_in[8];
    const float* pw1     = (const float*)d_in[9];
    const float* pw2     = (const float*)d_in[10];
    float* out = (float*)d_out;

    // 0) transpose + fp16-convert weights
    k_wt<<<dim3(8, 8, 3), dim3(32, 8)>>>(Wq, Wk, Wv);
    // 1) v = f @ Wv
    k_gemm_v<<<512, 512>>>(f_in);
    // 2) input grams S1=XtX, S2=YtY, T3=YtX (split-K partials) + reduce
    k_inpgram<<<dim3(NSPL, 2, 12), 512>>>(x_in, y_in);
    k_sred<<<dim3(256, 12), 256>>>();
    // 3) P1=S1*Wq, P2=S2*Wk, U3=T3*Wq
    k_mm2<<<dim3(2, 12), 512>>>();
    // 4) norms + G + softmax + fold into Wp -> Mt
    k_attn_m<<<32, 256>>>(Wq, Wk, Wp, rescale);
    // 5) positional branch writes d_out
    k_conv<<<dim3(64, 16, 4), 256>>>(pw1, pw2, out);
    // 6) out += v @ M[b] + bp
    k_gemm_out<<<512, 512>>>(bp, out);
}

// round 9
// speedup vs baseline: 1.2428x; 1.2428x over previous
#include <cuda_runtime.h>
#include <cuda_fp16.h>
#include <math.h>
#include <stdint.h>

#define B_    4
#define HW    128
#define NTOK  16384
#define C_    256
#define BN_   65536
#define GNC   16

// ---------------- static device scratch ----------------
__device__ __half g_q[BN_ * C_];
__device__ __half g_k[BN_ * C_];
__device__ __half g_v[BN_ * C_];
__device__ __half g_Wt[3 * C_ * C_];
__device__ __half g_Mt[B_ * C_ * C_];
__device__ float g_gram_part[GNC * 32 * 32 * 32];
__device__ float g_ssq_part[GNC * B_ * C_];
__device__ float g_ssk_part[GNC * B_ * C_];

__device__ __forceinline__ void mma_f16(float* c, const uint32_t* a, const uint32_t* b) {
    asm volatile(
        "mma.sync.aligned.m16n8k16.row.col.f32.f16.f16.f32 "
        "{%0,%1,%2,%3}, {%4,%5,%6,%7}, {%8,%9}, {%0,%1,%2,%3};"
        : "+f"(c[0]), "+f"(c[1]), "+f"(c[2]), "+f"(c[3])
        : "r"(a[0]), "r"(a[1]), "r"(a[2]), "r"(a[3]), "r"(b[0]), "r"(b[1]));
}
__device__ __forceinline__ void cp16(void* s, const void* g) {
    uint32_t sa = (uint32_t)__cvta_generic_to_shared(s);
    asm volatile("cp.async.cg.shared.global [%0], [%1], 16;" :: "r"(sa), "l"(g));
}
#define CP_COMMIT() asm volatile("cp.async.commit_group;" ::: "memory")
#define CP_WAIT(n)  asm volatile("cp.async.wait_group %0;" :: "n"(n) : "memory")

#define KC   16
#define SPH  24          // B row stride (halves)
#define SPF  20          // A fp32 row stride (floats)
#define QKV_SMEM (3 * 128 * SPF * 4 + 3 * 256 * SPH * 2)   // 67584 B

// =================== QKV GEMM: 3-stage cp.async, A fp32 staged ===================
// 512 thr = 16 warps (2m x 8n), block 128M x 256N, K=256 in 16 chunks.
__global__ void __launch_bounds__(512) k_gemm_qkv(
    const float* __restrict__ x, const float* __restrict__ y, const float* __restrict__ f)
{
    extern __shared__ char smem[];
    float*  Af = (float*)smem;                            // 3 x 128*SPF
    __half* Bh = (__half*)(smem + 3 * 128 * SPF * 4);     // 3 x 256*SPH

    const int z = blockIdx.y;
    const float* A = (z == 0) ? x : (z == 1) ? y : f;
    const __half* Bt = g_Wt + (size_t)z * 65536;
    __half* C = (z == 0) ? g_q : (z == 1) ? g_k : g_v;
    const int row0 = blockIdx.x * 128;

    const int t = threadIdx.x;
    const int warp = t >> 5, lane = t & 31;
    const int wm0 = (warp & 1) * 64;
    const int wn0 = (warp >> 1) * 32;
    const int g = lane >> 2;
    const int q = lane & 3;

    float acc[4][4][4];
#pragma unroll
    for (int mf = 0; mf < 4; mf++)
#pragma unroll
        for (int nf = 0; nf < 4; nf++)
#pragma unroll
            for (int r = 0; r < 4; r++) acc[mf][nf][r] = 0.f;

    const int ar = t >> 2, ak = (t & 3) * 4;     // A: 128 rows x 16 floats
    const float* Ab = A + (size_t)(row0 + ar) * 256 + ak;
    const int br = t >> 1, bk = (t & 1) * 8;     // B: 256 rows x 16 halves
    const __half* Bb = Bt + (size_t)br * 256 + bk;

    // prologue: chunks 0,1
#pragma unroll
    for (int pc = 0; pc < 2; pc++) {
        cp16(Af + pc * (128 * SPF) + ar * SPF + ak, Ab + pc * KC);
        cp16(Bh + pc * (256 * SPH) + br * SPH + bk, Bb + pc * KC);
        CP_COMMIT();
    }

    int st = 0;
    for (int c = 0; c < 16; c++) {
        if (c < 15) { CP_WAIT(1); } else { CP_WAIT(0); }
        __syncthreads();
        if (c < 14) {
            int ns = st + 2; if (ns >= 3) ns -= 3;
            cp16(Af + ns * (128 * SPF) + ar * SPF + ak, Ab + (c + 2) * KC);
            cp16(Bh + ns * (256 * SPH) + br * SPH + bk, Bb + (c + 2) * KC);
            CP_COMMIT();
        }
        const float*  As = Af + st * (128 * SPF);
        const __half* Bs = Bh + st * (256 * SPH);

        uint32_t bf[4][2];
#pragma unroll
        for (int nf = 0; nf < 4; nf++) {
            int n = wn0 + nf * 8 + g;
            bf[nf][0] = *(const uint32_t*)&Bs[n * SPH + 2 * q];
            bf[nf][1] = *(const uint32_t*)&Bs[n * SPH + 2 * q + 8];
        }
#pragma unroll
        for (int mf = 0; mf < 4; mf++) {
            int r = wm0 + mf * 16 + g;
            float2 f0 = *(const float2*)&As[r * SPF + 2 * q];
            float2 f1 = *(const float2*)&As[(r + 8) * SPF + 2 * q];
            float2 f2 = *(const float2*)&As[r * SPF + 2 * q + 8];
            float2 f3 = *(const float2*)&As[(r + 8) * SPF + 2 * q + 8];
            __half2 h0 = __float22half2_rn(f0);
            __half2 h1 = __float22half2_rn(f1);
            __half2 h2 = __float22half2_rn(f2);
            __half2 h3 = __float22half2_rn(f3);
            uint32_t af[4];
            af[0] = *(const uint32_t*)&h0;
            af[1] = *(const uint32_t*)&h1;
            af[2] = *(const uint32_t*)&h2;
            af[3] = *(const uint32_t*)&h3;
#pragma unroll
            for (int nf = 0; nf < 4; nf++)
                mma_f16(acc[mf][nf], af, bf[nf]);
        }
        st++; if (st >= 3) st -= 3;
    }

#pragma unroll
    for (int mf = 0; mf < 4; mf++) {
        int rbase = row0 + wm0 + mf * 16 + g;
#pragma unroll
        for (int nf = 0; nf < 4; nf++) {
            int cb = wn0 + nf * 8 + 2 * q;
            *(__half2*)(C + (size_t)rbase * 256 + cb)
                = __float22half2_rn(make_float2(acc[mf][nf][0], acc[mf][nf][1]));
            *(__half2*)(C + (size_t)(rbase + 8) * 256 + cb)
                = __float22half2_rn(make_float2(acc[mf][nf][2], acc[mf][nf][3]));
        }
    }
}

// ---- OUT: A fp16 (g_v) + B fp16 (g_Mt), accumulate into f32 d_out + bias ----
__global__ void __launch_bounds__(512) k_gemm_out(
    const float* __restrict__ bp, float* __restrict__ out)
{
    __shared__ __half As[2][128 * SPH];
    __shared__ __half Bs[2][256 * SPH];

    const int row0 = blockIdx.x * 128;
    const int b = row0 >> 14;
    const __half* Ab0 = g_v;
    const __half* Bt = g_Mt + (size_t)b * 65536;

    const int t = threadIdx.x;
    const int warp = t >> 5, lane = t & 31;
    const int wm0 = (warp & 1) * 64;
    const int wn0 = (warp >> 1) * 32;
    const int g = lane >> 2;
    const int q = lane & 3;

    float acc[4][4][4];
#pragma unroll
    for (int mf = 0; mf < 4; mf++)
#pragma unroll
        for (int nf = 0; nf < 4; nf++)
#pragma unroll
            for (int r = 0; r < 4; r++) acc[mf][nf][r] = 0.f;

    const int ar = t >> 1, ak = (t & 1) * 8;
    const __half* Ab = Ab0 + (size_t)(row0 + ar) * 256 + ak;
    const __half* Bb = Bt + (size_t)ar * 256 + ak;

    if (t < 256) cp16(&As[0][ar * SPH + ak], Ab);
    cp16(&Bs[0][ar * SPH + ak], Bb);
    CP_COMMIT();

    for (int c = 0; c < 16; c++) {
        const int st = c & 1;
        CP_WAIT(0);
        __syncthreads();
        if (c < 15) {
            const int k0 = (c + 1) * KC;
            if (t < 256) cp16(&As[st ^ 1][ar * SPH + ak], Ab + k0);
            cp16(&Bs[st ^ 1][ar * SPH + ak], Bb + k0);
            CP_COMMIT();
        }
        uint32_t bf[4][2];
#pragma unroll
        for (int nf = 0; nf < 4; nf++) {
            int n = wn0 + nf * 8 + g;
            bf[nf][0] = *(const uint32_t*)&Bs[st][n * SPH + 2 * q];
            bf[nf][1] = *(const uint32_t*)&Bs[st][n * SPH + 2 * q + 8];
        }
#pragma unroll
        for (int mf = 0; mf < 4; mf++) {
            int r = wm0 + mf * 16 + g;
            uint32_t af[4];
            af[0] = *(const uint32_t*)&As[st][r * SPH + 2 * q];
            af[1] = *(const uint32_t*)&As[st][(r + 8) * SPH + 2 * q];
            af[2] = *(const uint32_t*)&As[st][r * SPH + 2 * q + 8];
            af[3] = *(const uint32_t*)&As[st][(r + 8) * SPH + 2 * q + 8];
#pragma unroll
            for (int nf = 0; nf < 4; nf++)
                mma_f16(acc[mf][nf], af, bf[nf]);
        }
    }

#pragma unroll
    for (int mf = 0; mf < 4; mf++) {
        int rbase = row0 + wm0 + mf * 16 + g;
#pragma unroll
        for (int nf = 0; nf < 4; nf++) {
            int cb = wn0 + nf * 8 + 2 * q;
            float2 bb = *(const float2*)(bp + cb);
            float2* p0 = (float2*)(out + (size_t)rbase * 256 + cb);
            float2* p1 = (float2*)(out + (size_t)(rbase + 8) * 256 + cb);
            float2 o0 = *p0, o1 = *p1;
            o0.x += acc[mf][nf][0] + bb.x; o0.y += acc[mf][nf][1] + bb.y;
            o1.x += acc[mf][nf][2] + bb.x; o1.y += acc[mf][nf][3] + bb.y;
            *p0 = o0;
            *p1 = o1;
        }
    }
}

// =================== weight transpose + fp16 conversion ===================
__global__ void k_wt(const float* __restrict__ Wq, const float* __restrict__ Wk,
                     const float* __restrict__ Wv)
{
    int z = blockIdx.z;
    const float* W = (z == 0) ? Wq : (z == 1) ? Wk : Wv;
    __half* Wt = g_Wt + (size_t)z * 65536;
    __shared__ float tile[32][33];
    int tx = threadIdx.x, ty = threadIdx.y;
    int k0 = blockIdx.y * 32, n0 = blockIdx.x * 32;
#pragma unroll
    for (int i = 0; i < 4; i++)
        tile[ty + 8 * i][tx] = W[(size_t)(k0 + ty + 8 * i) * 256 + n0 + tx];
    __syncthreads();
#pragma unroll
    for (int i = 0; i < 4; i++)
        Wt[(size_t)(n0 + ty + 8 * i) * 256 + k0 + tx] = __float2half_rn(tile[tx][ty + 8 * i]);
}

// =================== gram + fused token norms (reads fp16 q/k) ===================
__global__ void __launch_bounds__(256) k_gram()
{
    int bh = blockIdx.y, b = bh >> 3, h = bh & 7;
    int t = threadIdx.x;
    int sub = t >> 6;
    int w64 = t & 63;
    int i4 = ((w64 >> 3) & 7) * 4;
    int j4 = (w64 & 7) * 4;
    __shared__ float qs[32][36], ks[32][36];
    __shared__ float red[4][32][32];
    __shared__ float rq[8][32], rk[8][32];

    float acc[4][4];
#pragma unroll
    for (int a = 0; a < 4; a++)
#pragma unroll
        for (int d = 0; d < 4; d++) acc[a][d] = 0.f;
    float sq = 0.f, sk = 0.f;

    const int lc = t & 31, lr0 = t >> 5;
    size_t base = ((size_t)b * NTOK + (size_t)blockIdx.x * 1024) * 256 + h * 32 + lc;

    for (int n0 = 0; n0 < 1024; n0 += 32) {
#pragma unroll
        for (int s = 0; s < 4; s++) {
            int r = lr0 + 8 * s;
            float qv = __half2float(g_q[base + (size_t)(n0 + r) * 256]);
            float kv = __half2float(g_k[base + (size_t)(n0 + r) * 256]);
            qs[r][lc] = qv; ks[r][lc] = kv;
            sq += qv * qv; sk += kv * kv;
        }
        __syncthreads();
#pragma unroll
        for (int nn = 0; nn < 8; nn++) {
            int n = sub + nn * 4;
            float4 qv = *(const float4*)&qs[n][j4];
            float4 kv = *(const float4*)&ks[n][i4];
            acc[0][0] += kv.x * qv.x; acc[0][1] += kv.x * qv.y;
            acc[0][2] += kv.x * qv.z; acc[0][3] += kv.x * qv.w;
            acc[1][0] += kv.y * qv.x; acc[1][1] += kv.y * qv.y;
            acc[1][2] += kv.y * qv.z; acc[1][3] += kv.y * qv.w;
            acc[2][0] += kv.z * qv.x; acc[2][1] += kv.z * qv.y;
            acc[2][2] += kv.z * qv.z; acc[2][3] += kv.z * qv.w;
            acc[3][0] += kv.w * qv.x; acc[3][1] += kv.w * qv.y;
            acc[3][2] += kv.w * qv.z; acc[3][3] += kv.w * qv.w;
        }
        __syncthreads();
    }

#pragma unroll
    for (int di = 0; di < 4; di++)
#pragma unroll
        for (int dj = 0; dj < 4; dj++)
            red[sub][i4 + di][j4 + dj] = acc[di][dj];
    rq[lr0][lc] = sq;
    rk[lr0][lc] = sk;
    __syncthreads();

#pragma unroll
    for (int e = t; e < 1024; e += 256) {
        int i = e >> 5, j = e & 31;
        g_gram_part[(((size_t)blockIdx.x * 32 + bh) * 32 + i) * 32 + j]
            = red[0][i][j] + red[1][i][j] + red[2][i][j] + red[3][i][j];
    }
    if (t < 32) {
        float aq = 0.f, ak = 0.f;
#pragma unroll
        for (int i = 0; i < 8; i++) { aq += rq[i][t]; ak += rk[i][t]; }
        g_ssq_part[((size_t)blockIdx.x * B_ + b) * C_ + h * 32 + t] = aq;
        g_ssk_part[((size_t)blockIdx.x * B_ + b) * C_ + h * 32 + t] = ak;
    }
}

// softmax + fold attn into Wp -> TRANSPOSED Mt[b][c][h*32+j] fp16
__global__ void k_attn_m(const float* __restrict__ Wp, const float* __restrict__ rescale)
{
    int bh = blockIdx.x, b = bh >> 3, h = bh & 7;
    int t = threadIdx.x;
    __shared__ float attn[32][32];
    __shared__ float wp[32][256];
    __shared__ float nq[32], nk[32];

#pragma unroll
    for (int s = 0; s < 32; s++) {
        int idx = t + s * 256;
        wp[idx >> 8][idx & 255] = Wp[(size_t)(h * 32 + (idx >> 8)) * 256 + (idx & 255)];
    }
    if (t < 32) {
        float sq = 0.f, sk = 0.f;
#pragma unroll
        for (int ch = 0; ch < GNC; ch++) {
            sq += g_ssq_part[((size_t)ch * B_ + b) * C_ + h * 32 + t];
            sk += g_ssk_part[((size_t)ch * B_ + b) * C_ + h * 32 + t];
        }
        nq[t] = fmaxf(sqrtf(sq), 1e-12f);
        nk[t] = fmaxf(sqrtf(sk), 1e-12f);
    }
    __syncthreads();

    float resc = rescale[h];
    int w = t >> 5, lane = t & 31;
    for (int i = w; i < 32; i += 8) {
        float g = 0.f;
#pragma unroll
        for (int ch = 0; ch < GNC; ch++)
            g += g_gram_part[(((size_t)ch * 32 + bh) * 32 + i) * 32 + lane];
        float val = g / (nk[i] * nq[lane]) * resc;
        float m = val;
#pragma unroll
        for (int o = 16; o; o >>= 1) m = fmaxf(m, __shfl_xor_sync(0xffffffffu, m, o));
        float e = expf(val - m);
        float ssum = e;
#pragma unroll
        for (int o = 16; o; o >>= 1) ssum += __shfl_xor_sync(0xffffffffu, ssum, o);
        attn[i][lane] = e / ssum;
    }
    __syncthreads();

    float acc[32];
#pragma unroll
    for (int j = 0; j < 32; j++) acc[j] = 0.f;
#pragma unroll 4
    for (int i = 0; i < 32; i++) {
        float wpv = wp[i][t];
#pragma unroll
        for (int j = 0; j < 32; j++) acc[j] += attn[i][j] * wpv;
    }
#pragma unroll
    for (int j = 0; j < 32; j++)
        g_Mt[((size_t)b * 256 + t) * 256 + h * 32 + j] = __float2half_rn(acc[j]);
}

// =================== fused positional branch (reads fp16 v) ===================
__device__ __forceinline__ float gelu_exact(float x)
{
    return 0.5f * x * (1.0f + erff(x * 0.7071067811865475f));
}

__global__ void __launch_bounds__(256) k_conv(
    const float* __restrict__ pw1, const float* __restrict__ pw2,
    float* __restrict__ out)
{
    __shared__ float vs[20][20][16];
    __shared__ float t1[18][18][16];
    const int t = threadIdx.x;
    const int cl = t & 15;
    const int tp = t >> 4;
    const int c = (blockIdx.y << 4) + cl;
    const int tx0 = (blockIdx.x & 7) * 16, ty0 = (blockIdx.x >> 3) * 16;
    const int b = blockIdx.z;

    float w1[9], w2[9];
#pragma unroll
    for (int i = 0; i < 9; i++) {
        w1[i] = pw1[i * 256 + c];
        w2[i] = pw2[i * 256 + c];
    }

    for (int p = tp; p < 400; p += 16) {
        int py = p / 20, px = p - py * 20;
        int gy = ty0 + py - 2, gx = tx0 + px - 2;
        float v = 0.f;
        if (gy >= 0 && gy < 128 && gx >= 0 && gx < 128)
            v = __half2float(g_v[(((size_t)(b * 128 + gy)) * 128 + gx) * 256 + c]);
        vs[py][px][cl] = v;
    }
    __syncthreads();

    for (int p = tp; p < 324; p += 16) {
        int py = p / 18, px = p - py * 18;
        float acc = 0.f;
#pragma unroll
        for (int dy = 0; dy < 3; dy++)
#pragma unroll
            for (int dx = 0; dx < 3; dx++)
                acc += vs[py + dy][px + dx][cl] * w1[dy * 3 + dx];
        int gy = ty0 + py - 1, gx = tx0 + px - 1;
        float val = (gy >= 0 && gy < 128 && gx >= 0 && gx < 128) ? gelu_exact(acc) : 0.f;
        t1[py][px][cl] = val;
    }
    __syncthreads();

    for (int p = tp; p < 256; p += 16) {
        int py = p >> 4, px = p & 15;
        float acc = 0.f;
#pragma unroll
        for (int dy = 0; dy < 3; dy++)
#pragma unroll
            for (int dx = 0; dx < 3; dx++)
                acc += t1[py + dy][px + dx][cl] * w2[dy * 3 + dx];
        out[(((size_t)(b * 128 + ty0 + py)) * 128 + tx0 + px) * 256 + c] = acc;
    }
}

extern "C" void kernel_launch(void* const* d_in, const int* in_sizes, int n_in,
                              void* d_out, int out_size)
{
    const float* x_in    = (const float*)d_in[0];
    const float* y_in    = (const float*)d_in[1];
    const float* f_in    = (const float*)d_in[2];
    const float* Wq      = (const float*)d_in[3];
    const float* Wk      = (const float*)d_in[4];
    const float* Wv      = (const float*)d_in[5];
    const float* rescale = (const float*)d_in[6];
    const float* Wp      = (const float*)d_in[7];
    const float* bp      = (const float*)d_in[8];
    const float* pw1     = (const float*)d_in[9];
    const float* pw2     = (const float*)d_in[10];
    float* out = (float*)d_out;

    cudaFuncSetAttribute(k_gemm_qkv, cudaFuncAttributeMaxDynamicSharedMemorySize, QKV_SMEM);

    // 0) transpose + fp16-convert weights
    k_wt<<<dim3(8, 8, 3), dim3(32, 8)>>>(Wq, Wk, Wv);
    // 1) q/k/v projections (fp16 mma, 3-stage cp.async, fp32 A staging)
    k_gemm_qkv<<<dim3(512, 3), 512, QKV_SMEM>>>(x_in, y_in, f_in);
    // 2) per-head Gram partials + fused token norms
    k_gram<<<dim3(GNC, 32), 256>>>();
    // 3) softmax + fold attention into Wp -> per-batch Mt (fp16)
    k_attn_m<<<32, 256>>>(Wp, rescale);
    // 4) fused positional branch writes d_out
    k_conv<<<dim3(64, 16, 4), 256>>>(pw1, pw2, out);
    // 5) out += v @ M[b] + bp
    k_gemm_out<<<512, 512>>>(bp, out);
}

// round 10
// speedup vs baseline: 1.3319x; 1.0717x over previous
#include <cuda_runtime.h>
#include <cuda_fp16.h>
#include <math.h>
#include <stdint.h>

#define B_    4
#define NTOK  16384
#define C_    256
#define BN_   65536

// ---------------- static device scratch ----------------
__device__ __half g_v[BN_ * C_];
__device__ __half g_Wt[3 * C_ * C_];
__device__ __half g_Mt[B_ * C_ * C_];
__device__ float g_gram_part[128 * 8 * 32 * 32];   // 4 MB [blk][h][i][j]
__device__ float g_ssq_part[128 * C_];
__device__ float g_ssk_part[128 * C_];

__device__ __forceinline__ void mma_f16(float* c, const uint32_t* a, const uint32_t* b) {
    asm volatile(
        "mma.sync.aligned.m16n8k16.row.col.f32.f16.f16.f32 "
        "{%0,%1,%2,%3}, {%4,%5,%6,%7}, {%8,%9}, {%0,%1,%2,%3};"
        : "+f"(c[0]), "+f"(c[1]), "+f"(c[2]), "+f"(c[3])
        : "r"(a[0]), "r"(a[1]), "r"(a[2]), "r"(a[3]), "r"(b[0]), "r"(b[1]));
}
__device__ __forceinline__ void cp16(void* s, const void* g) {
    uint32_t sa = (uint32_t)__cvta_generic_to_shared(s);
    asm volatile("cp.async.cg.shared.global [%0], [%1], 16;" :: "r"(sa), "l"(g));
}
#define CP_COMMIT() asm volatile("cp.async.commit_group;" ::: "memory")
#define CP_WAIT0()  asm volatile("cp.async.wait_group 0;" ::: "memory")

__device__ __forceinline__ void ldsm4t(uint32_t* r, const __half* p) {
    uint32_t a = (uint32_t)__cvta_generic_to_shared(p);
    asm volatile("ldmatrix.sync.aligned.m8n8.x4.trans.shared.b16 {%0,%1,%2,%3}, [%4];"
                 : "=r"(r[0]), "=r"(r[1]), "=r"(r[2]), "=r"(r[3]) : "r"(a));
}
__device__ __forceinline__ void ldsm2t(uint32_t* r, const __half* p) {
    uint32_t a = (uint32_t)__cvta_generic_to_shared(p);
    asm volatile("ldmatrix.sync.aligned.m8n8.x2.trans.shared.b16 {%0,%1}, [%2];"
                 : "=r"(r[0]), "=r"(r[1]) : "r"(a));
}

#define KC   16
#define SPH  24
#define SPF  20
#define RS   264

// ---- k_qkgram smem layout (bytes) ----
#define KT_OFF  (128 * RS)                     // in halves
#define AF_OFF  (2 * 128 * RS * 2)             // byte offset
#define BH_OFF  (AF_OFF + 2 * 128 * SPF * 4)
#define QKG_SMEM (BH_OFF + 2 * 256 * SPH * 2)  // 180224

// projection pass: tile[128x256 fp16 in smem] = A[128x256 fp32] @ Bt^T
// 512 thr, 16 warps (2m x 8n), K=256 in 16 chunks, 2-stage cp.async.
__device__ __forceinline__ void proj_pass(
    const float* __restrict__ Asrc, const __half* __restrict__ Bt,
    __half* tile, float* Af, __half* Bh, int t)
{
    const int warp = t >> 5, lane = t & 31;
    const int wm0 = (warp & 1) * 64, wn0 = (warp >> 1) * 32;
    const int g = lane >> 2, q = lane & 3;
    const int ar = t >> 2, ak = (t & 3) * 4;
    const int br = t >> 1, bk = (t & 1) * 8;
    const float* Ab = Asrc + (size_t)ar * 256 + ak;
    const __half* Bb = Bt + (size_t)br * 256 + bk;

    float acc[4][4][4];
#pragma unroll
    for (int mf = 0; mf < 4; mf++)
#pragma unroll
        for (int nf = 0; nf < 4; nf++)
#pragma unroll
            for (int r = 0; r < 4; r++) acc[mf][nf][r] = 0.f;

    cp16(Af + ar * SPF + ak, Ab);
    cp16(Bh + br * SPH + bk, Bb);
    CP_COMMIT();

    for (int c = 0; c < 16; c++) {
        const int st = c & 1;
        CP_WAIT0();
        __syncthreads();
        if (c < 15) {
            const int k0 = (c + 1) * KC;
            cp16(Af + (st ^ 1) * (128 * SPF) + ar * SPF + ak, Ab + k0);
            cp16(Bh + (st ^ 1) * (256 * SPH) + br * SPH + bk, Bb + k0);
            CP_COMMIT();
        }
        const float*  As = Af + st * (128 * SPF);
        const __half* Bs = Bh + st * (256 * SPH);

        uint32_t bf[4][2];
#pragma unroll
        for (int nf = 0; nf < 4; nf++) {
            int n = wn0 + nf * 8 + g;
            bf[nf][0] = *(const uint32_t*)&Bs[n * SPH + 2 * q];
            bf[nf][1] = *(const uint32_t*)&Bs[n * SPH + 2 * q + 8];
        }
#pragma unroll
        for (int mf = 0; mf < 4; mf++) {
            int r = wm0 + mf * 16 + g;
            float2 f0 = *(const float2*)&As[r * SPF + 2 * q];
            float2 f1 = *(const float2*)&As[(r + 8) * SPF + 2 * q];
            float2 f2 = *(const float2*)&As[r * SPF + 2 * q + 8];
            float2 f3 = *(const float2*)&As[(r + 8) * SPF + 2 * q + 8];
            __half2 h0 = __float22half2_rn(f0);
            __half2 h1 = __float22half2_rn(f1);
            __half2 h2 = __float22half2_rn(f2);
            __half2 h3 = __float22half2_rn(f3);
            uint32_t af[4];
            af[0] = *(const uint32_t*)&h0;
            af[1] = *(const uint32_t*)&h1;
            af[2] = *(const uint32_t*)&h2;
            af[3] = *(const uint32_t*)&h3;
#pragma unroll
            for (int nf = 0; nf < 4; nf++)
                mma_f16(acc[mf][nf], af, bf[nf]);
        }
    }

    // epilogue: write fp16 tile to smem
#pragma unroll
    for (int mf = 0; mf < 4; mf++) {
        int r = wm0 + mf * 16 + g;
#pragma unroll
        for (int nf = 0; nf < 4; nf++) {
            int cb = wn0 + nf * 8 + 2 * q;
            *(__half2*)&tile[r * RS + cb]
                = __float22half2_rn(make_float2(acc[mf][nf][0], acc[mf][nf][1]));
            *(__half2*)&tile[(r + 8) * RS + cb]
                = __float22half2_rn(make_float2(acc[mf][nf][2], acc[mf][nf][3]));
        }
    }
}

// ================= fused Q/K projection + Gram + norms =================
// grid 128 (512 tokens each), 512 thr. q/k never leave SMEM.
__global__ void __launch_bounds__(512) k_qkgram(
    const float* __restrict__ x, const float* __restrict__ y)
{
    extern __shared__ char smem[];
    __half* qtile = (__half*)smem;
    __half* ktile = qtile + KT_OFF;
    float*  Af = (float*)(smem + AF_OFF);
    __half* Bh = (__half*)(smem + BH_OFF);

    const int blk = blockIdx.x;
    const size_t tokbase = (size_t)blk * 512;
    const int t = threadIdx.x;
    const int warp = t >> 5, lane = t & 31;

    // gram per-warp state: head = warp>>1, rows mi..mi+15
    const int h = warp >> 1, mi = (warp & 1) * 16;
    const int lrowA = (lane & 7) + ((lane >> 4) << 3);
    const int lcolA = ((lane >> 3) & 1) << 3;
    const int lrowB = (lane & 7) + (((lane >> 3) & 1) << 3);
    float gacc[4][4];
#pragma unroll
    for (int nf = 0; nf < 4; nf++)
#pragma unroll
        for (int r = 0; r < 4; r++) gacc[nf][r] = 0.f;

    const int cpair = t & 127, rg = t >> 7;
    float sq0 = 0.f, sq1 = 0.f, sk0 = 0.f, sk1 = 0.f;

    for (int s = 0; s < 4; s++) {
        const size_t tb = (tokbase + s * 128) * 256;
        proj_pass(x + tb, g_Wt, qtile, Af, Bh, t);
        proj_pass(y + tb, g_Wt + 65536, ktile, Af, Bh, t);
        __syncthreads();   // tiles visible to all

        // gram: G[h][i][j] += sum_n ktile[n][h32+i] * qtile[n][h32+j]
#pragma unroll
        for (int k0 = 0; k0 < 128; k0 += 16) {
            uint32_t af[4];
            ldsm4t(af, &ktile[(k0 + lrowA) * RS + h * 32 + mi + lcolA]);
#pragma unroll
            for (int nf = 0; nf < 4; nf++) {
                uint32_t bf[2];
                ldsm2t(bf, &qtile[(k0 + lrowB) * RS + h * 32 + nf * 8]);
                mma_f16(gacc[nf], af, bf);
            }
        }
        // norms: sumsq over this subtile's 128 rows
#pragma unroll 4
        for (int r = rg * 32; r < rg * 32 + 32; r++) {
            __half2 hq = *(const __half2*)&qtile[r * RS + 2 * cpair];
            __half2 hk = *(const __half2*)&ktile[r * RS + 2 * cpair];
            float2 fq = __half22float2(hq), fk = __half22float2(hk);
            sq0 += fq.x * fq.x; sq1 += fq.y * fq.y;
            sk0 += fk.x * fk.x; sk1 += fk.y * fk.y;
        }
        __syncthreads();   // before next subtile overwrites tiles
    }

    // write gram partials [blk][h][32][32]
    {
        const int g2 = lane >> 2, q2 = lane & 3;
        float* gp = g_gram_part + ((size_t)blk * 8 + h) * 1024;
#pragma unroll
        for (int nf = 0; nf < 4; nf++) {
            int cb = nf * 8 + 2 * q2;
            *(float2*)&gp[(mi + g2) * 32 + cb] = make_float2(gacc[nf][0], gacc[nf][1]);
            *(float2*)&gp[(mi + g2 + 8) * 32 + cb] = make_float2(gacc[nf][2], gacc[nf][3]);
        }
    }
    // norm partials via scratch (reuse Af region)
    float* scr = (float*)(smem + AF_OFF);
    scr[rg * 256 + 2 * cpair] = sq0;
    scr[rg * 256 + 2 * cpair + 1] = sq1;
    scr[1024 + rg * 256 + 2 * cpair] = sk0;
    scr[1024 + rg * 256 + 2 * cpair + 1] = sk1;
    __syncthreads();
    if (t < 256) {
        float a = scr[t] + scr[256 + t] + scr[512 + t] + scr[768 + t];
        float bb = scr[1024 + t] + scr[1280 + t] + scr[1536 + t] + scr[1792 + t];
        g_ssq_part[(size_t)blk * 256 + t] = a;
        g_ssk_part[(size_t)blk * 256 + t] = bb;
    }
}

// ================= v = f @ Wv (R7-proven GEMM) =================
__global__ void __launch_bounds__(512) k_gemm_v(const float* __restrict__ f)
{
    __shared__ __half As[2][128 * SPH];
    __shared__ __half Bs[2][256 * SPH];

    const float* A = f;
    const __half* Bt = g_Wt + 2 * 65536;
    __half* C = g_v;
    const int row0 = blockIdx.x * 128;

    const int t = threadIdx.x;
    const int warp = t >> 5, lane = t & 31;
    const int wm0 = (warp & 1) * 64;
    const int wn0 = (warp >> 1) * 32;
    const int g = lane >> 2;
    const int q = lane & 3;

    float acc[4][4][4];
#pragma unroll
    for (int mf = 0; mf < 4; mf++)
#pragma unroll
        for (int nf = 0; nf < 4; nf++)
#pragma unroll
            for (int r = 0; r < 4; r++) acc[mf][nf][r] = 0.f;

    const int ar = t >> 2, ak = (t & 3) * 4;
    const float* Ab = A + (size_t)(row0 + ar) * 256 + ak;
    const int br = t >> 1, bk = (t & 1) * 8;
    const __half* Bb = Bt + (size_t)br * 256 + bk;

    {
        float4 pa = *(const float4*)(Ab);
        cp16(&Bs[0][br * SPH + bk], Bb);
        CP_COMMIT();
        __half2 h[2];
        h[0] = __float22half2_rn(make_float2(pa.x, pa.y));
        h[1] = __float22half2_rn(make_float2(pa.z, pa.w));
        *(uint2*)&As[0][ar * SPH + ak] = *(const uint2*)h;
    }

    for (int c = 0; c < 16; c++) {
        const int st = c & 1;
        CP_WAIT0();
        __syncthreads();
        if (c < 15) {
            const int k0 = (c + 1) * KC;
            float4 pa = *(const float4*)(Ab + k0);
            cp16(&Bs[st ^ 1][br * SPH + bk], Bb + k0);
            CP_COMMIT();
            __half2 h[2];
            h[0] = __float22half2_rn(make_float2(pa.x, pa.y));
            h[1] = __float22half2_rn(make_float2(pa.z, pa.w));
            *(uint2*)&As[st ^ 1][ar * SPH + ak] = *(const uint2*)h;
        }

        uint32_t bf[4][2];
#pragma unroll
        for (int nf = 0; nf < 4; nf++) {
            int n = wn0 + nf * 8 + g;
            bf[nf][0] = *(const uint32_t*)&Bs[st][n * SPH + 2 * q];
            bf[nf][1] = *(const uint32_t*)&Bs[st][n * SPH + 2 * q + 8];
        }
#pragma unroll
        for (int mf = 0; mf < 4; mf++) {
            int r = wm0 + mf * 16 + g;
            uint32_t af[4];
            af[0] = *(const uint32_t*)&As[st][r * SPH + 2 * q];
            af[1] = *(const uint32_t*)&As[st][(r + 8) * SPH + 2 * q];
            af[2] = *(const uint32_t*)&As[st][r * SPH + 2 * q + 8];
            af[3] = *(const uint32_t*)&As[st][(r + 8) * SPH + 2 * q + 8];
#pragma unroll
            for (int nf = 0; nf < 4; nf++)
                mma_f16(acc[mf][nf], af, bf[nf]);
        }
    }

#pragma unroll
    for (int mf = 0; mf < 4; mf++) {
        int rbase = row0 + wm0 + mf * 16 + g;
#pragma unroll
        for (int nf = 0; nf < 4; nf++) {
            int cb = wn0 + nf * 8 + 2 * q;
            *(__half2*)(C + (size_t)rbase * 256 + cb)
                = __float22half2_rn(make_float2(acc[mf][nf][0], acc[mf][nf][1]));
            *(__half2*)(C + (size_t)(rbase + 8) * 256 + cb)
                = __float22half2_rn(make_float2(acc[mf][nf][2], acc[mf][nf][3]));
        }
    }
}

// ---- OUT: A fp16 (g_v) + B fp16 (g_Mt), accumulate into f32 d_out + bias ----
__global__ void __launch_bounds__(512) k_gemm_out(
    const float* __restrict__ bp, float* __restrict__ out)
{
    __shared__ __half As[2][128 * SPH];
    __shared__ __half Bs[2][256 * SPH];

    const int row0 = blockIdx.x * 128;
    const int b = row0 >> 14;
    const __half* Ab0 = g_v;
    const __half* Bt = g_Mt + (size_t)b * 65536;

    const int t = threadIdx.x;
    const int warp = t >> 5, lane = t & 31;
    const int wm0 = (warp & 1) * 64;
    const int wn0 = (warp >> 1) * 32;
    const int g = lane >> 2;
    const int q = lane & 3;

    float acc[4][4][4];
#pragma unroll
    for (int mf = 0; mf < 4; mf++)
#pragma unroll
        for (int nf = 0; nf < 4; nf++)
#pragma unroll
            for (int r = 0; r < 4; r++) acc[mf][nf][r] = 0.f;

    const int ar = t >> 1, ak = (t & 1) * 8;
    const __half* Ab = Ab0 + (size_t)(row0 + ar) * 256 + ak;
    const __half* Bb = Bt + (size_t)ar * 256 + ak;

    if (t < 256) cp16(&As[0][ar * SPH + ak], Ab);
    cp16(&Bs[0][ar * SPH + ak], Bb);
    CP_COMMIT();

    for (int c = 0; c < 16; c++) {
        const int st = c & 1;
        CP_WAIT0();
        __syncthreads();
        if (c < 15) {
            const int k0 = (c + 1) * KC;
            if (t < 256) cp16(&As[st ^ 1][ar * SPH + ak], Ab + k0);
            cp16(&Bs[st ^ 1][ar * SPH + ak], Bb + k0);
            CP_COMMIT();
        }
        uint32_t bf[4][2];
#pragma unroll
        for (int nf = 0; nf < 4; nf++) {
            int n = wn0 + nf * 8 + g;
            bf[nf][0] = *(const uint32_t*)&Bs[st][n * SPH + 2 * q];
            bf[nf][1] = *(const uint32_t*)&Bs[st][n * SPH + 2 * q + 8];
        }
#pragma unroll
        for (int mf = 0; mf < 4; mf++) {
            int r = wm0 + mf * 16 + g;
            uint32_t af[4];
            af[0] = *(const uint32_t*)&As[st][r * SPH + 2 * q];
            af[1] = *(const uint32_t*)&As[st][(r + 8) * SPH + 2 * q];
            af[2] = *(const uint32_t*)&As[st][r * SPH + 2 * q + 8];
            af[3] = *(const uint32_t*)&As[st][(r + 8) * SPH + 2 * q + 8];
#pragma unroll
            for (int nf = 0; nf < 4; nf++)
                mma_f16(acc[mf][nf], af, bf[nf]);
        }
    }

#pragma unroll
    for (int mf = 0; mf < 4; mf++) {
        int rbase = row0 + wm0 + mf * 16 + g;
#pragma unroll
        for (int nf = 0; nf < 4; nf++) {
            int cb = wn0 + nf * 8 + 2 * q;
            float2 bb = *(const float2*)(bp + cb);
            float2* p0 = (float2*)(out + (size_t)rbase * 256 + cb);
            float2* p1 = (float2*)(out + (size_t)(rbase + 8) * 256 + cb);
            float2 o0 = *p0, o1 = *p1;
            o0.x += acc[mf][nf][0] + bb.x; o0.y += acc[mf][nf][1] + bb.y;
            o1.x += acc[mf][nf][2] + bb.x; o1.y += acc[mf][nf][3] + bb.y;
            *p0 = o0;
            *p1 = o1;
        }
    }
}

// =================== weight transpose + fp16 conversion ===================
__global__ void k_wt(const float* __restrict__ Wq, const float* __restrict__ Wk,
                     const float* __restrict__ Wv)
{
    int z = blockIdx.z;
    const float* W = (z == 0) ? Wq : (z == 1) ? Wk : Wv;
    __half* Wt = g_Wt + (size_t)z * 65536;
    __shared__ float tile[32][33];
    int tx = threadIdx.x, ty = threadIdx.y;
    int k0 = blockIdx.y * 32, n0 = blockIdx.x * 32;
#pragma unroll
    for (int i = 0; i < 4; i++)
        tile[ty + 8 * i][tx] = W[(size_t)(k0 + ty + 8 * i) * 256 + n0 + tx];
    __syncthreads();
#pragma unroll
    for (int i = 0; i < 4; i++)
        Wt[(size_t)(n0 + ty + 8 * i) * 256 + k0 + tx] = __float2half_rn(tile[tx][ty + 8 * i]);
}

// ============ norms + G + softmax + fold into Wp -> Mt (32 chunks) ============
__global__ void k_attn_m(const float* __restrict__ Wp, const float* __restrict__ rescale)
{
    int bh = blockIdx.x, b = bh >> 3, h = bh & 7;
    int t = threadIdx.x;
    __shared__ float attn[32][32];
    __shared__ float wp[32][256];
    __shared__ float nq[32], nk[32];

#pragma unroll
    for (int s = 0; s < 32; s++) {
        int idx = t + s * 256;
        wp[idx >> 8][idx & 255] = Wp[(size_t)(h * 32 + (idx >> 8)) * 256 + (idx & 255)];
    }
    if (t < 32) {
        float sq = 0.f, sk = 0.f;
#pragma unroll
        for (int ch = 0; ch < 32; ch++) {
            sq += g_ssq_part[(size_t)(b * 32 + ch) * 256 + h * 32 + t];
            sk += g_ssk_part[(size_t)(b * 32 + ch) * 256 + h * 32 + t];
        }
        nq[t] = fmaxf(sqrtf(sq), 1e-12f);
        nk[t] = fmaxf(sqrtf(sk), 1e-12f);
    }
    __syncthreads();

    float resc = rescale[h];
    int w = t >> 5, lane = t & 31;
    for (int i = w; i < 32; i += 8) {
        float g = 0.f;
#pragma unroll
        for (int ch = 0; ch < 32; ch++)
            g += g_gram_part[((size_t)(b * 32 + ch) * 8 + h) * 1024 + i * 32 + lane];
        float val = g / (nk[i] * nq[lane]) * resc;
        float m = val;
#pragma unroll
        for (int o = 16; o; o >>= 1) m = fmaxf(m, __shfl_xor_sync(0xffffffffu, m, o));
        float e = expf(val - m);
        float ssum = e;
#pragma unroll
        for (int o = 16; o; o >>= 1) ssum += __shfl_xor_sync(0xffffffffu, ssum, o);
        attn[i][lane] = e / ssum;
    }
    __syncthreads();

    float acc[32];
#pragma unroll
    for (int j = 0; j < 32; j++) acc[j] = 0.f;
#pragma unroll 4
    for (int i = 0; i < 32; i++) {
        float wpv = wp[i][t];
#pragma unroll
        for (int j = 0; j < 32; j++) acc[j] += attn[i][j] * wpv;
    }
#pragma unroll
    for (int j = 0; j < 32; j++)
        g_Mt[((size_t)b * 256 + t) * 256 + h * 32 + j] = __float2half_rn(acc[j]);
}

// =================== fused positional branch (reads fp16 v) ===================
__device__ __forceinline__ float gelu_exact(float x)
{
    return 0.5f * x * (1.0f + erff(x * 0.7071067811865475f));
}

__global__ void __launch_bounds__(256) k_conv(
    const float* __restrict__ pw1, const float* __restrict__ pw2,
    float* __restrict__ out)
{
    __shared__ float vs[20][20][16];
    __shared__ float t1[18][18][16];
    const int t = threadIdx.x;
    const int cl = t & 15;
    const int tp = t >> 4;
    const int c = (blockIdx.y << 4) + cl;
    const int tx0 = (blockIdx.x & 7) * 16, ty0 = (blockIdx.x >> 3) * 16;
    const int b = blockIdx.z;

    float w1[9], w2[9];
#pragma unroll
    for (int i = 0; i < 9; i++) {
        w1[i] = pw1[i * 256 + c];
        w2[i] = pw2[i * 256 + c];
    }

    for (int p = tp; p < 400; p += 16) {
        int py = p / 20, px = p - py * 20;
        int gy = ty0 + py - 2, gx = tx0 + px - 2;
        float v = 0.f;
        if (gy >= 0 && gy < 128 && gx >= 0 && gx < 128)
            v = __half2float(g_v[(((size_t)(b * 128 + gy)) * 128 + gx) * 256 + c]);
        vs[py][px][cl] = v;
    }
    __syncthreads();

    for (int p = tp; p < 324; p += 16) {
        int py = p / 18, px = p - py * 18;
        float acc = 0.f;
#pragma unroll
        for (int dy = 0; dy < 3; dy++)
#pragma unroll
            for (int dx = 0; dx < 3; dx++)
                acc += vs[py + dy][px + dx][cl] * w1[dy * 3 + dx];
        int gy = ty0 + py - 1, gx = tx0 + px - 1;
        float val = (gy >= 0 && gy < 128 && gx >= 0 && gx < 128) ? gelu_exact(acc) : 0.f;
        t1[py][px][cl] = val;
    }
    __syncthreads();

    for (int p = tp; p < 256; p += 16) {
        int py = p >> 4, px = p & 15;
        float acc = 0.f;
#pragma unroll
        for (int dy = 0; dy < 3; dy++)
#pragma unroll
            for (int dx = 0; dx < 3; dx++)
                acc += t1[py + dy][px + dx][cl] * w2[dy * 3 + dx];
        out[(((size_t)(b * 128 + ty0 + py)) * 128 + tx0 + px) * 256 + c] = acc;
    }
}

extern "C" void kernel_launch(void* const* d_in, const int* in_sizes, int n_in,
                              void* d_out, int out_size)
{
    const float* x_in    = (const float*)d_in[0];
    const float* y_in    = (const float*)d_in[1];
    const float* f_in    = (const float*)d_in[2];
    const float* Wq      = (const float*)d_in[3];
    const float* Wk      = (const float*)d_in[4];
    const float* Wv      = (const float*)d_in[5];
    const float* rescale = (const float*)d_in[6];
    const float* Wp      = (const float*)d_in[7];
    const float* bp      = (const float*)d_in[8];
    const float* pw1     = (const float*)d_in[9];
    const float* pw2     = (const float*)d_in[10];
    float* out = (float*)d_out;

    cudaFuncSetAttribute(k_qkgram, cudaFuncAttributeMaxDynamicSharedMemorySize, QKG_SMEM);

    // 1) transpose + fp16-convert weights
    k_wt<<<dim3(8, 8, 3), dim3(32, 8)>>>(Wq, Wk, Wv);
    // 2) v = f @ Wv
    k_gemm_v<<<512, 512>>>(f_in);
    // 3) positional branch writes d_out
    k_conv<<<dim3(64, 16, 4), 256>>>(pw1, pw2, out);
    // 4) fused Q/K projection + Gram + norms (q/k never hit DRAM) [profiled slot]
    k_qkgram<<<128, 512, QKG_SMEM>>>(x_in, y_in);
    // 5) softmax + fold attention into Wp -> per-batch Mt (fp16)
    k_attn_m<<<32, 256>>>(Wp, rescale);
    // 6) out += v @ M[b] + bp
    k_gemm_out<<<512, 512>>>(bp, out);
}

// round 11
// speedup vs baseline: 1.3869x; 1.0413x over previous
#include <cuda_runtime.h>
#include <cuda_fp16.h>
#include <math.h>
#include <stdint.h>

#define B_    4
#define NTOK  16384
#define C_    256
#define BN_   65536

// ---------------- static device scratch ----------------
__device__ __half g_v[BN_ * C_];
__device__ __half g_Wt[3 * C_ * C_];
__device__ __half g_Mt[B_ * C_ * C_];
__device__ float g_gram_part[128 * 8 * 32 * 32];   // 4 MB [blk][h][i][j]
__device__ float g_ssq_part[128 * C_];
__device__ float g_ssk_part[128 * C_];

__device__ __forceinline__ void mma_f16(float* c, const uint32_t* a, const uint32_t* b) {
    asm volatile(
        "mma.sync.aligned.m16n8k16.row.col.f32.f16.f16.f32 "
        "{%0,%1,%2,%3}, {%4,%5,%6,%7}, {%8,%9}, {%0,%1,%2,%3};"
        : "+f"(c[0]), "+f"(c[1]), "+f"(c[2]), "+f"(c[3])
        : "r"(a[0]), "r"(a[1]), "r"(a[2]), "r"(a[3]), "r"(b[0]), "r"(b[1]));
}
__device__ __forceinline__ void cp16(void* s, const void* g) {
    uint32_t sa = (uint32_t)__cvta_generic_to_shared(s);
    asm volatile("cp.async.cg.shared.global [%0], [%1], 16;" :: "r"(sa), "l"(g));
}
#define CP_COMMIT() asm volatile("cp.async.commit_group;" ::: "memory")
#define CP_WAIT(n)  asm volatile("cp.async.wait_group %0;" :: "n"(n) : "memory")

__device__ __forceinline__ void ldsm4t(uint32_t* r, const __half* p) {
    uint32_t a = (uint32_t)__cvta_generic_to_shared(p);
    asm volatile("ldmatrix.sync.aligned.m8n8.x4.trans.shared.b16 {%0,%1,%2,%3}, [%4];"
                 : "=r"(r[0]), "=r"(r[1]), "=r"(r[2]), "=r"(r[3]) : "r"(a));
}
__device__ __forceinline__ void ldsm2t(uint32_t* r, const __half* p) {
    uint32_t a = (uint32_t)__cvta_generic_to_shared(p);
    asm volatile("ldmatrix.sync.aligned.m8n8.x2.trans.shared.b16 {%0,%1}, [%2];"
                 : "=r"(r[0]), "=r"(r[1]) : "r"(a));
}

#define KC   16
#define SPH  24
#define RS   264

// ---- k_qkgram smem layout ----
#define KT_OFF  (128 * RS)                       // halves
#define AH_OFF  (2 * 128 * RS * 2)               // bytes: 135168
#define BH_OFF  (AH_OFF + 2 * 128 * SPH * 2)     // +12288 = 147456
#define QKG_SMEM (BH_OFF + 4 * 256 * SPH * 2)    // +49152 = 196608

// projection pass: tile[128x256 fp16 smem] = A[128x256 fp32] @ Bt^T
// A: LDG prefetch distance 2 + fp16 STS (2-stage); B: 4-stage cp.async.
// nacc[8]: accumulates per-thread col sumsq of the rounded fp16 outputs.
__device__ __forceinline__ void proj_pass(
    const float* __restrict__ Asrc, const __half* __restrict__ Bt,
    __half* tile, __half* Ah, __half* Bh, int t, float* nacc)
{
    const int warp = t >> 5, lane = t & 31;
    const int wm0 = (warp & 1) * 64, wn0 = (warp >> 1) * 32;
    const int g = lane >> 2, q = lane & 3;
    const int ar = t >> 2, ak4 = (t & 3) * 4;
    const int br = t >> 1, bk = (t & 1) * 8;
    const float* Ab = Asrc + (size_t)ar * 256 + ak4;
    const __half* Bb = Bt + (size_t)br * 256 + bk;

    float acc[4][4][4];
#pragma unroll
    for (int mf = 0; mf < 4; mf++)
#pragma unroll
        for (int nf = 0; nf < 4; nf++)
#pragma unroll
            for (int r = 0; r < 4; r++) acc[mf][nf][r] = 0.f;

    // prologue: B chunks 0..2 via cp.async; A chunk 0 staged, chunks 1,2 in regs
    cp16(Bh + 0 * (256 * SPH) + br * SPH + bk, Bb);
    CP_COMMIT();
    cp16(Bh + 1 * (256 * SPH) + br * SPH + bk, Bb + KC);
    CP_COMMIT();
    cp16(Bh + 2 * (256 * SPH) + br * SPH + bk, Bb + 2 * KC);
    CP_COMMIT();
    {
        float4 p0 = *(const float4*)(Ab);
        __half2 h[2];
        h[0] = __float22half2_rn(make_float2(p0.x, p0.y));
        h[1] = __float22half2_rn(make_float2(p0.z, p0.w));
        *(uint2*)&Ah[ar * SPH + ak4] = *(const uint2*)h;
    }
    float4 par0 = *(const float4*)(Ab + KC);
    float4 par1 = *(const float4*)(Ab + 2 * KC);

    for (int c = 0; c < 16; c++) {
        if (c <= 13)      { CP_WAIT(2); }
        else if (c == 14) { CP_WAIT(1); }
        else              { CP_WAIT(0); }
        __syncthreads();
        if (c < 15) {
            __half2 h[2];
            h[0] = __float22half2_rn(make_float2(par0.x, par0.y));
            h[1] = __float22half2_rn(make_float2(par0.z, par0.w));
            *(uint2*)&Ah[((c + 1) & 1) * (128 * SPH) + ar * SPH + ak4] = *(const uint2*)h;
            par0 = par1;
        }
        if (c + 3 < 16) {
            par1 = *(const float4*)(Ab + (c + 3) * KC);
            cp16(Bh + ((c + 3) & 3) * (256 * SPH) + br * SPH + bk, Bb + (c + 3) * KC);
            CP_COMMIT();
        }

        const __half* As = Ah + (c & 1) * (128 * SPH);
        const __half* Bs = Bh + (c & 3) * (256 * SPH);

        uint32_t bf[4][2];
#pragma unroll
        for (int nf = 0; nf < 4; nf++) {
            int n = wn0 + nf * 8 + g;
            bf[nf][0] = *(const uint32_t*)&Bs[n * SPH + 2 * q];
            bf[nf][1] = *(const uint32_t*)&Bs[n * SPH + 2 * q + 8];
        }
#pragma unroll
        for (int mf = 0; mf < 4; mf++) {
            int r = wm0 + mf * 16 + g;
            uint32_t af[4];
            af[0] = *(const uint32_t*)&As[r * SPH + 2 * q];
            af[1] = *(const uint32_t*)&As[(r + 8) * SPH + 2 * q];
            af[2] = *(const uint32_t*)&As[r * SPH + 2 * q + 8];
            af[3] = *(const uint32_t*)&As[(r + 8) * SPH + 2 * q + 8];
#pragma unroll
            for (int nf = 0; nf < 4; nf++)
                mma_f16(acc[mf][nf], af, bf[nf]);
        }
    }

    // epilogue: write fp16 tile + accumulate col sumsq of rounded values
#pragma unroll
    for (int mf = 0; mf < 4; mf++) {
        int r = wm0 + mf * 16 + g;
#pragma unroll
        for (int nf = 0; nf < 4; nf++) {
            int cb = wn0 + nf * 8 + 2 * q;
            __half2 h2a = __float22half2_rn(make_float2(acc[mf][nf][0], acc[mf][nf][1]));
            __half2 h2b = __float22half2_rn(make_float2(acc[mf][nf][2], acc[mf][nf][3]));
            *(__half2*)&tile[r * RS + cb] = h2a;
            *(__half2*)&tile[(r + 8) * RS + cb] = h2b;
            float2 fa = __half22float2(h2a), fb = __half22float2(h2b);
            nacc[nf * 2 + 0] += fa.x * fa.x + fb.x * fb.x;
            nacc[nf * 2 + 1] += fa.y * fa.y + fb.y * fb.y;
        }
    }
}

// ================= fused Q/K projection + Gram + norms =================
__global__ void __launch_bounds__(512) k_qkgram(
    const float* __restrict__ x, const float* __restrict__ y)
{
    extern __shared__ char smem[];
    __half* qtile = (__half*)smem;
    __half* ktile = qtile + KT_OFF;
    __half* Ah = (__half*)(smem + AH_OFF);
    __half* Bh = (__half*)(smem + BH_OFF);

    const int blk = blockIdx.x;
    const size_t tokbase = (size_t)blk * 512;
    const int t = threadIdx.x;
    const int warp = t >> 5, lane = t & 31;

    const int h = warp >> 1, mi = (warp & 1) * 16;
    const int lrowA = (lane & 7) + ((lane >> 4) << 3);
    const int lcolA = ((lane >> 3) & 1) << 3;
    const int lrowB = (lane & 7) + (((lane >> 3) & 1) << 3);
    float gacc[4][4];
#pragma unroll
    for (int nf = 0; nf < 4; nf++)
#pragma unroll
        for (int r = 0; r < 4; r++) gacc[nf][r] = 0.f;

    float nq8[8], nk8[8];
#pragma unroll
    for (int i = 0; i < 8; i++) { nq8[i] = 0.f; nk8[i] = 0.f; }

    for (int s = 0; s < 4; s++) {
        const size_t tb = (tokbase + s * 128) * 256;
        proj_pass(x + tb, g_Wt, qtile, Ah, Bh, t, nq8);
        proj_pass(y + tb, g_Wt + 65536, ktile, Ah, Bh, t, nk8);
        __syncthreads();   // tiles visible to all

        // gram: G[h][i][j] += sum_n ktile[n][h32+i] * qtile[n][h32+j]
#pragma unroll
        for (int k0 = 0; k0 < 128; k0 += 16) {
            uint32_t af[4];
            ldsm4t(af, &ktile[(k0 + lrowA) * RS + h * 32 + mi + lcolA]);
#pragma unroll
            for (int nf = 0; nf < 4; nf++) {
                uint32_t bf[2];
                ldsm2t(bf, &qtile[(k0 + lrowB) * RS + h * 32 + nf * 8]);
                mma_f16(gacc[nf], af, bf);
            }
        }
        __syncthreads();   // before next subtile overwrites tiles
    }

    // write gram partials [blk][h][32][32]
    {
        const int g2 = lane >> 2, q2 = lane & 3;
        float* gp = g_gram_part + ((size_t)blk * 8 + h) * 1024;
#pragma unroll
        for (int nf = 0; nf < 4; nf++) {
            int cb = nf * 8 + 2 * q2;
            *(float2*)&gp[(mi + g2) * 32 + cb] = make_float2(gacc[nf][0], gacc[nf][1]);
            *(float2*)&gp[(mi + g2 + 8) * 32 + cb] = make_float2(gacc[nf][2], gacc[nf][3]);
        }
    }

    // norm partials: butterfly over g, cross-warp via smem (reuse Ah region)
#pragma unroll
    for (int i = 0; i < 8; i++) {
#pragma unroll
        for (int off = 4; off <= 16; off <<= 1) {
            nq8[i] += __shfl_xor_sync(0xffffffffu, nq8[i], off);
            nk8[i] += __shfl_xor_sync(0xffffffffu, nk8[i], off);
        }
    }
    float* nsq = (float*)(smem + AH_OFF);         // [16][32]
    float* nsk = nsq + 16 * 32;                   // [16][32]
    if (lane < 4) {
#pragma unroll
        for (int nf = 0; nf < 4; nf++) {
#pragma unroll
            for (int e = 0; e < 2; e++) {
                nsq[warp * 32 + nf * 8 + 2 * lane + e] = nq8[nf * 2 + e];
                nsk[warp * 32 + nf * 8 + 2 * lane + e] = nk8[nf * 2 + e];
            }
        }
    }
    __syncthreads();
    if (t < 256) {
        int j = t >> 5, loc = t & 31;
        g_ssq_part[(size_t)blk * 256 + t] = nsq[(2 * j) * 32 + loc] + nsq[(2 * j + 1) * 32 + loc];
        g_ssk_part[(size_t)blk * 256 + t] = nsk[(2 * j) * 32 + loc] + nsk[(2 * j + 1) * 32 + loc];
    }
}

// ================= v = f @ Wv (R7-proven GEMM) =================
__global__ void __launch_bounds__(512) k_gemm_v(const float* __restrict__ f)
{
    __shared__ __half As[2][128 * SPH];
    __shared__ __half Bs[2][256 * SPH];

    const float* A = f;
    const __half* Bt = g_Wt + 2 * 65536;
    __half* C = g_v;
    const int row0 = blockIdx.x * 128;

    const int t = threadIdx.x;
    const int warp = t >> 5, lane = t & 31;
    const int wm0 = (warp & 1) * 64;
    const int wn0 = (warp >> 1) * 32;
    const int g = lane >> 2;
    const int q = lane & 3;

    float acc[4][4][4];
#pragma unroll
    for (int mf = 0; mf < 4; mf++)
#pragma unroll
        for (int nf = 0; nf < 4; nf++)
#pragma unroll
            for (int r = 0; r < 4; r++) acc[mf][nf][r] = 0.f;

    const int ar = t >> 2, ak = (t & 3) * 4;
    const float* Ab = A + (size_t)(row0 + ar) * 256 + ak;
    const int br = t >> 1, bk = (t & 1) * 8;
    const __half* Bb = Bt + (size_t)br * 256 + bk;

    {
        float4 pa = *(const float4*)(Ab);
        cp16(&Bs[0][br * SPH + bk], Bb);
        CP_COMMIT();
        __half2 h[2];
        h[0] = __float22half2_rn(make_float2(pa.x, pa.y));
        h[1] = __float22half2_rn(make_float2(pa.z, pa.w));
        *(uint2*)&As[0][ar * SPH + ak] = *(const uint2*)h;
    }

    for (int c = 0; c < 16; c++) {
        const int st = c & 1;
        CP_WAIT(0);
        __syncthreads();
        if (c < 15) {
            const int k0 = (c + 1) * KC;
            float4 pa = *(const float4*)(Ab + k0);
            cp16(&Bs[st ^ 1][br * SPH + bk], Bb + k0);
            CP_COMMIT();
            __half2 h[2];
            h[0] = __float22half2_rn(make_float2(pa.x, pa.y));
            h[1] = __float22half2_rn(make_float2(pa.z, pa.w));
            *(uint2*)&As[st ^ 1][ar * SPH + ak] = *(const uint2*)h;
        }

        uint32_t bf[4][2];
#pragma unroll
        for (int nf = 0; nf < 4; nf++) {
            int n = wn0 + nf * 8 + g;
            bf[nf][0] = *(const uint32_t*)&Bs[st][n * SPH + 2 * q];
            bf[nf][1] = *(const uint32_t*)&Bs[st][n * SPH + 2 * q + 8];
        }
#pragma unroll
        for (int mf = 0; mf < 4; mf++) {
            int r = wm0 + mf * 16 + g;
            uint32_t af[4];
            af[0] = *(const uint32_t*)&As[st][r * SPH + 2 * q];
            af[1] = *(const uint32_t*)&As[st][(r + 8) * SPH + 2 * q];
            af[2] = *(const uint32_t*)&As[st][r * SPH + 2 * q + 8];
            af[3] = *(const uint32_t*)&As[st][(r + 8) * SPH + 2 * q + 8];
#pragma unroll
            for (int nf = 0; nf < 4; nf++)
                mma_f16(acc[mf][nf], af, bf[nf]);
        }
    }

#pragma unroll
    for (int mf = 0; mf < 4; mf++) {
        int rbase = row0 + wm0 + mf * 16 + g;
#pragma unroll
        for (int nf = 0; nf < 4; nf++) {
            int cb = wn0 + nf * 8 + 2 * q;
            *(__half2*)(C + (size_t)rbase * 256 + cb)
                = __float22half2_rn(make_float2(acc[mf][nf][0], acc[mf][nf][1]));
            *(__half2*)(C + (size_t)(rbase + 8) * 256 + cb)
                = __float22half2_rn(make_float2(acc[mf][nf][2], acc[mf][nf][3]));
        }
    }
}

// ---- OUT: A fp16 (g_v) + B fp16 (g_Mt), accumulate into f32 d_out + bias ----
__global__ void __launch_bounds__(512) k_gemm_out(
    const float* __restrict__ bp, float* __restrict__ out)
{
    __shared__ __half As[2][128 * SPH];
    __shared__ __half Bs[2][256 * SPH];

    const int row0 = blockIdx.x * 128;
    const int b = row0 >> 14;
    const __half* Ab0 = g_v;
    const __half* Bt = g_Mt + (size_t)b * 65536;

    const int t = threadIdx.x;
    const int warp = t >> 5, lane = t & 31;
    const int wm0 = (warp & 1) * 64;
    const int wn0 = (warp >> 1) * 32;
    const int g = lane >> 2;
    const int q = lane & 3;

    float acc[4][4][4];
#pragma unroll
    for (int mf = 0; mf < 4; mf++)
#pragma unroll
        for (int nf = 0; nf < 4; nf++)
#pragma unroll
            for (int r = 0; r < 4; r++) acc[mf][nf][r] = 0.f;

    const int ar = t >> 1, ak = (t & 1) * 8;
    const __half* Ab = Ab0 + (size_t)(row0 + ar) * 256 + ak;
    const __half* Bb = Bt + (size_t)ar * 256 + ak;

    if (t < 256) cp16(&As[0][ar * SPH + ak], Ab);
    cp16(&Bs[0][ar * SPH + ak], Bb);
    CP_COMMIT();

    for (int c = 0; c < 16; c++) {
        const int st = c & 1;
        CP_WAIT(0);
        __syncthreads();
        if (c < 15) {
            const int k0 = (c + 1) * KC;
            if (t < 256) cp16(&As[st ^ 1][ar * SPH + ak], Ab + k0);
            cp16(&Bs[st ^ 1][ar * SPH + ak], Bb + k0);
            CP_COMMIT();
        }
        uint32_t bf[4][2];
#pragma unroll
        for (int nf = 0; nf < 4; nf++) {
            int n = wn0 + nf * 8 + g;
            bf[nf][0] = *(const uint32_t*)&Bs[st][n * SPH + 2 * q];
            bf[nf][1] = *(const uint32_t*)&Bs[st][n * SPH + 2 * q + 8];
        }
#pragma unroll
        for (int mf = 0; mf < 4; mf++) {
            int r = wm0 + mf * 16 + g;
            uint32_t af[4];
            af[0] = *(const uint32_t*)&As[st][r * SPH + 2 * q];
            af[1] = *(const uint32_t*)&As[st][(r + 8) * SPH + 2 * q];
            af[2] = *(const uint32_t*)&As[st][r * SPH + 2 * q + 8];
            af[3] = *(const uint32_t*)&As[st][(r + 8) * SPH + 2 * q + 8];
#pragma unroll
            for (int nf = 0; nf < 4; nf++)
                mma_f16(acc[mf][nf], af, bf[nf]);
        }
    }

#pragma unroll
    for (int mf = 0; mf < 4; mf++) {
        int rbase = row0 + wm0 + mf * 16 + g;
#pragma unroll
        for (int nf = 0; nf < 4; nf++) {
            int cb = wn0 + nf * 8 + 2 * q;
            float2 bb = *(const float2*)(bp + cb);
            float2* p0 = (float2*)(out + (size_t)rbase * 256 + cb);
            float2* p1 = (float2*)(out + (size_t)(rbase + 8) * 256 + cb);
            float2 o0 = *p0, o1 = *p1;
            o0.x += acc[mf][nf][0] + bb.x; o0.y += acc[mf][nf][1] + bb.y;
            o1.x += acc[mf][nf][2] + bb.x; o1.y += acc[mf][nf][3] + bb.y;
            *p0 = o0;
            *p1 = o1;
        }
    }
}

// =================== weight transpose + fp16 conversion ===================
__global__ void k_wt(const float* __restrict__ Wq, const float* __restrict__ Wk,
                     const float* __restrict__ Wv)
{
    int z = blockIdx.z;
    const float* W = (z == 0) ? Wq : (z == 1) ? Wk : Wv;
    __half* Wt = g_Wt + (size_t)z * 65536;
    __shared__ float tile[32][33];
    int tx = threadIdx.x, ty = threadIdx.y;
    int k0 = blockIdx.y * 32, n0 = blockIdx.x * 32;
#pragma unroll
    for (int i = 0; i < 4; i++)
        tile[ty + 8 * i][tx] = W[(size_t)(k0 + ty + 8 * i) * 256 + n0 + tx];
    __syncthreads();
#pragma unroll
    for (int i = 0; i < 4; i++)
        Wt[(size_t)(n0 + ty + 8 * i) * 256 + k0 + tx] = __float2half_rn(tile[tx][ty + 8 * i]);
}

// ============ norms + G + softmax + fold into Wp -> Mt (32 chunks) ============
__global__ void k_attn_m(const float* __restrict__ Wp, const float* __restrict__ rescale)
{
    int bh = blockIdx.x, b = bh >> 3, h = bh & 7;
    int t = threadIdx.x;
    __shared__ float attn[32][32];
    __shared__ float wp[32][256];
    __shared__ float nq[32], nk[32];

#pragma unroll
    for (int s = 0; s < 32; s++) {
        int idx = t + s * 256;
        wp[idx >> 8][idx & 255] = Wp[(size_t)(h * 32 + (idx >> 8)) * 256 + (idx & 255)];
    }
    if (t < 32) {
        float sq = 0.f, sk = 0.f;
#pragma unroll
        for (int ch = 0; ch < 32; ch++) {
            sq += g_ssq_part[(size_t)(b * 32 + ch) * 256 + h * 32 + t];
            sk += g_ssk_part[(size_t)(b * 32 + ch) * 256 + h * 32 + t];
        }
        nq[t] = fmaxf(sqrtf(sq), 1e-12f);
        nk[t] = fmaxf(sqrtf(sk), 1e-12f);
    }
    __syncthreads();

    float resc = rescale[h];
    int w = t >> 5, lane = t & 31;
    for (int i = w; i < 32; i += 8) {
        float g = 0.f;
#pragma unroll
        for (int ch = 0; ch < 32; ch++)
            g += g_gram_part[((size_t)(b * 32 + ch) * 8 + h) * 1024 + i * 32 + lane];
        float val = g / (nk[i] * nq[lane]) * resc;
        float m = val;
#pragma unroll
        for (int o = 16; o; o >>= 1) m = fmaxf(m, __shfl_xor_sync(0xffffffffu, m, o));
        float e = expf(val - m);
        float ssum = e;
#pragma unroll
        for (int o = 16; o; o >>= 1) ssum += __shfl_xor_sync(0xffffffffu, ssum, o);
        attn[i][lane] = e / ssum;
    }
    __syncthreads();

    float acc[32];
#pragma unroll
    for (int j = 0; j < 32; j++) acc[j] = 0.f;
#pragma unroll 4
    for (int i = 0; i < 32; i++) {
        float wpv = wp[i][t];
#pragma unroll
        for (int j = 0; j < 32; j++) acc[j] += attn[i][j] * wpv;
    }
#pragma unroll
    for (int j = 0; j < 32; j++)
        g_Mt[((size_t)b * 256 + t) * 256 + h * 32 + j] = __float2half_rn(acc[j]);
}

// =================== fused positional branch (reads fp16 v) ===================
__device__ __forceinline__ float gelu_exact(float x)
{
    return 0.5f * x * (1.0f + erff(x * 0.7071067811865475f));
}

__global__ void __launch_bounds__(256) k_conv(
    const float* __restrict__ pw1, const float* __restrict__ pw2,
    float* __restrict__ out)
{
    __shared__ float vs[20][20][16];
    __shared__ float t1[18][18][16];
    const int t = threadIdx.x;
    const int cl = t & 15;
    const int tp = t >> 4;
    const int c = (blockIdx.y << 4) + cl;
    const int tx0 = (blockIdx.x & 7) * 16, ty0 = (blockIdx.x >> 3) * 16;
    const int b = blockIdx.z;

    float w1[9], w2[9];
#pragma unroll
    for (int i = 0; i < 9; i++) {
        w1[i] = pw1[i * 256 + c];
        w2[i] = pw2[i * 256 + c];
    }

    for (int p = tp; p < 400; p += 16) {
        int py = p / 20, px = p - py * 20;
        int gy = ty0 + py - 2, gx = tx0 + px - 2;
        float v = 0.f;
        if (gy >= 0 && gy < 128 && gx >= 0 && gx < 128)
            v = __half2float(g_v[(((size_t)(b * 128 + gy)) * 128 + gx) * 256 + c]);
        vs[py][px][cl] = v;
    }
    __syncthreads();

    for (int p = tp; p < 324; p += 16) {
        int py = p / 18, px = p - py * 18;
        float acc = 0.f;
#pragma unroll
        for (int dy = 0; dy < 3; dy++)
#pragma unroll
            for (int dx = 0; dx < 3; dx++)
                acc += vs[py + dy][px + dx][cl] * w1[dy * 3 + dx];
        int gy = ty0 + py - 1, gx = tx0 + px - 1;
        float val = (gy >= 0 && gy < 128 && gx >= 0 && gx < 128) ? gelu_exact(acc) : 0.f;
        t1[py][px][cl] = val;
    }
    __syncthreads();

    for (int p = tp; p < 256; p += 16) {
        int py = p >> 4, px = p & 15;
        float acc = 0.f;
#pragma unroll
        for (int dy = 0; dy < 3; dy++)
#pragma unroll
            for (int dx = 0; dx < 3; dx++)
                acc += t1[py + dy][px + dx][cl] * w2[dy * 3 + dx];
        out[(((size_t)(b * 128 + ty0 + py)) * 128 + tx0 + px) * 256 + c] = acc;
    }
}

extern "C" void kernel_launch(void* const* d_in, const int* in_sizes, int n_in,
                              void* d_out, int out_size)
{
    const float* x_in    = (const float*)d_in[0];
    const float* y_in    = (const float*)d_in[1];
    const float* f_in    = (const float*)d_in[2];
    const float* Wq      = (const float*)d_in[3];
    const float* Wk      = (const float*)d_in[4];
    const float* Wv      = (const float*)d_in[5];
    const float* rescale = (const float*)d_in[6];
    const float* Wp      = (const float*)d_in[7];
    const float* bp      = (const float*)d_in[8];
    const float* pw1     = (const float*)d_in[9];
    const float* pw2     = (const float*)d_in[10];
    float* out = (float*)d_out;

    cudaFuncSetAttribute(k_qkgram, cudaFuncAttributeMaxDynamicSharedMemorySize, QKG_SMEM);

    // 1) transpose + fp16-convert weights
    k_wt<<<dim3(8, 8, 3), dim3(32, 8)>>>(Wq, Wk, Wv);
    // 2) v = f @ Wv
    k_gemm_v<<<512, 512>>>(f_in);
    // 3) positional branch writes d_out
    k_conv<<<dim3(64, 16, 4), 256>>>(pw1, pw2, out);
    // 4) fused Q/K projection + Gram + norms (deep pipeline, fp16 A frags)
    k_qkgram<<<128, 512, QKG_SMEM>>>(x_in, y_in);
    // 5) softmax + fold attention into Wp -> per-batch Mt (fp16)
    k_attn_m<<<32, 256>>>(Wp, rescale);
    // 6) out += v @ M[b] + bp
    k_gemm_out<<<512, 512>>>(bp, out);
}

// round 12
// speedup vs baseline: 1.4465x; 1.0429x over previous
#include <cuda_runtime.h>
#include <cuda_fp16.h>
#include <math.h>
#include <stdint.h>

#define B_    4
#define NTOK  16384
#define C_    256
#define BN_   65536

// ---------------- static device scratch ----------------
__device__ __half g_v[BN_ * C_];
__device__ __half g_Wt[3 * C_ * C_];
__device__ __half g_Mt[B_ * C_ * C_];
__device__ float g_gram_part[128 * 8 * 32 * 32];   // 4 MB [blk][h][i][j]
__device__ float g_ssq_part[128 * C_];
__device__ float g_ssk_part[128 * C_];

__device__ __forceinline__ void mma_f16(float* c, const uint32_t* a, const uint32_t* b) {
    asm volatile(
        "mma.sync.aligned.m16n8k16.row.col.f32.f16.f16.f32 "
        "{%0,%1,%2,%3}, {%4,%5,%6,%7}, {%8,%9}, {%0,%1,%2,%3};"
        : "+f"(c[0]), "+f"(c[1]), "+f"(c[2]), "+f"(c[3])
        : "r"(a[0]), "r"(a[1]), "r"(a[2]), "r"(a[3]), "r"(b[0]), "r"(b[1]));
}
__device__ __forceinline__ void cp16(void* s, const void* g) {
    uint32_t sa = (uint32_t)__cvta_generic_to_shared(s);
    asm volatile("cp.async.cg.shared.global [%0], [%1], 16;" :: "r"(sa), "l"(g));
}
#define CP_COMMIT() asm volatile("cp.async.commit_group;" ::: "memory")
#define CP_WAIT(n)  asm volatile("cp.async.wait_group %0;" :: "n"(n) : "memory")

__device__ __forceinline__ void ldsm4t(uint32_t* r, const __half* p) {
    uint32_t a = (uint32_t)__cvta_generic_to_shared(p);
    asm volatile("ldmatrix.sync.aligned.m8n8.x4.trans.shared.b16 {%0,%1,%2,%3}, [%4];"
                 : "=r"(r[0]), "=r"(r[1]), "=r"(r[2]), "=r"(r[3]) : "r"(a));
}
__device__ __forceinline__ void ldsm2t(uint32_t* r, const __half* p) {
    uint32_t a = (uint32_t)__cvta_generic_to_shared(p);
    asm volatile("ldmatrix.sync.aligned.m8n8.x2.trans.shared.b16 {%0,%1}, [%2];"
                 : "=r"(r[0]), "=r"(r[1]) : "r"(a));
}

#define KC   16
#define SPH  24
#define RS   264

// ---- k_qkgram smem layout ----
#define KT_OFF  (128 * RS)                       // halves
#define AH_OFF  (2 * 128 * RS * 2)               // bytes: 135168
#define BH_OFF  (AH_OFF + 2 * 128 * SPH * 2)     // +12288 = 147456
#define QKG_SMEM (BH_OFF + 4 * 256 * SPH * 2)    // +49152 = 196608

// projection pass: tile[128x256 fp16 smem] = A[128x256 fp32] @ Bt^T
// A: LDG prefetch distance 2 + fp16 STS (2-stage); B: 4-stage cp.async.
__device__ __forceinline__ void proj_pass(
    const float* __restrict__ Asrc, const __half* __restrict__ Bt,
    __half* tile, __half* Ah, __half* Bh, int t, float* nacc)
{
    const int warp = t >> 5, lane = t & 31;
    const int wm0 = (warp & 1) * 64, wn0 = (warp >> 1) * 32;
    const int g = lane >> 2, q = lane & 3;
    const int ar = t >> 2, ak4 = (t & 3) * 4;
    const int br = t >> 1, bk = (t & 1) * 8;
    const float* Ab = Asrc + (size_t)ar * 256 + ak4;
    const __half* Bb = Bt + (size_t)br * 256 + bk;

    float acc[4][4][4];
#pragma unroll
    for (int mf = 0; mf < 4; mf++)
#pragma unroll
        for (int nf = 0; nf < 4; nf++)
#pragma unroll
            for (int r = 0; r < 4; r++) acc[mf][nf][r] = 0.f;

    cp16(Bh + 0 * (256 * SPH) + br * SPH + bk, Bb);
    CP_COMMIT();
    cp16(Bh + 1 * (256 * SPH) + br * SPH + bk, Bb + KC);
    CP_COMMIT();
    cp16(Bh + 2 * (256 * SPH) + br * SPH + bk, Bb + 2 * KC);
    CP_COMMIT();
    {
        float4 p0 = *(const float4*)(Ab);
        __half2 h[2];
        h[0] = __float22half2_rn(make_float2(p0.x, p0.y));
        h[1] = __float22half2_rn(make_float2(p0.z, p0.w));
        *(uint2*)&Ah[ar * SPH + ak4] = *(const uint2*)h;
    }
    float4 par0 = *(const float4*)(Ab + KC);
    float4 par1 = *(const float4*)(Ab + 2 * KC);

    for (int c = 0; c < 16; c++) {
        if (c <= 13)      { CP_WAIT(2); }
        else if (c == 14) { CP_WAIT(1); }
        else              { CP_WAIT(0); }
        __syncthreads();
        if (c < 15) {
            __half2 h[2];
            h[0] = __float22half2_rn(make_float2(par0.x, par0.y));
            h[1] = __float22half2_rn(make_float2(par0.z, par0.w));
            *(uint2*)&Ah[((c + 1) & 1) * (128 * SPH) + ar * SPH + ak4] = *(const uint2*)h;
            par0 = par1;
        }
        if (c + 3 < 16) {
            par1 = *(const float4*)(Ab + (c + 3) * KC);
            cp16(Bh + ((c + 3) & 3) * (256 * SPH) + br * SPH + bk, Bb + (c + 3) * KC);
            CP_COMMIT();
        }

        const __half* As = Ah + (c & 1) * (128 * SPH);
        const __half* Bs = Bh + (c & 3) * (256 * SPH);

        uint32_t bf[4][2];
#pragma unroll
        for (int nf = 0; nf < 4; nf++) {
            int n = wn0 + nf * 8 + g;
            bf[nf][0] = *(const uint32_t*)&Bs[n * SPH + 2 * q];
            bf[nf][1] = *(const uint32_t*)&Bs[n * SPH + 2 * q + 8];
        }
#pragma unroll
        for (int mf = 0; mf < 4; mf++) {
            int r = wm0 + mf * 16 + g;
            uint32_t af[4];
            af[0] = *(const uint32_t*)&As[r * SPH + 2 * q];
            af[1] = *(const uint32_t*)&As[(r + 8) * SPH + 2 * q];
            af[2] = *(const uint32_t*)&As[r * SPH + 2 * q + 8];
            af[3] = *(const uint32_t*)&As[(r + 8) * SPH + 2 * q + 8];
#pragma unroll
            for (int nf = 0; nf < 4; nf++)
                mma_f16(acc[mf][nf], af, bf[nf]);
        }
    }

#pragma unroll
    for (int mf = 0; mf < 4; mf++) {
        int r = wm0 + mf * 16 + g;
#pragma unroll
        for (int nf = 0; nf < 4; nf++) {
            int cb = wn0 + nf * 8 + 2 * q;
            __half2 h2a = __float22half2_rn(make_float2(acc[mf][nf][0], acc[mf][nf][1]));
            __half2 h2b = __float22half2_rn(make_float2(acc[mf][nf][2], acc[mf][nf][3]));
            *(__half2*)&tile[r * RS + cb] = h2a;
            *(__half2*)&tile[(r + 8) * RS + cb] = h2b;
            float2 fa = __half22float2(h2a), fb = __half22float2(h2b);
            nacc[nf * 2 + 0] += fa.x * fa.x + fb.x * fb.x;
            nacc[nf * 2 + 1] += fa.y * fa.y + fb.y * fb.y;
        }
    }
}

// ================= fused Q/K projection + Gram + norms =================
__global__ void __launch_bounds__(512) k_qkgram(
    const float* __restrict__ x, const float* __restrict__ y)
{
    extern __shared__ char smem[];
    __half* qtile = (__half*)smem;
    __half* ktile = qtile + KT_OFF;
    __half* Ah = (__half*)(smem + AH_OFF);
    __half* Bh = (__half*)(smem + BH_OFF);

    const int blk = blockIdx.x;
    const size_t tokbase = (size_t)blk * 512;
    const int t = threadIdx.x;
    const int warp = t >> 5, lane = t & 31;

    const int h = warp >> 1, mi = (warp & 1) * 16;
    const int lrowA = (lane & 7) + ((lane >> 4) << 3);
    const int lcolA = ((lane >> 3) & 1) << 3;
    const int lrowB = (lane & 7) + (((lane >> 3) & 1) << 3);
    float gacc[4][4];
#pragma unroll
    for (int nf = 0; nf < 4; nf++)
#pragma unroll
        for (int r = 0; r < 4; r++) gacc[nf][r] = 0.f;

    float nq8[8], nk8[8];
#pragma unroll
    for (int i = 0; i < 8; i++) { nq8[i] = 0.f; nk8[i] = 0.f; }

    for (int s = 0; s < 4; s++) {
        const size_t tb = (tokbase + s * 128) * 256;
        proj_pass(x + tb, g_Wt, qtile, Ah, Bh, t, nq8);
        proj_pass(y + tb, g_Wt + 65536, ktile, Ah, Bh, t, nk8);
        __syncthreads();

#pragma unroll
        for (int k0 = 0; k0 < 128; k0 += 16) {
            uint32_t af[4];
            ldsm4t(af, &ktile[(k0 + lrowA) * RS + h * 32 + mi + lcolA]);
#pragma unroll
            for (int nf = 0; nf < 4; nf++) {
                uint32_t bf[2];
                ldsm2t(bf, &qtile[(k0 + lrowB) * RS + h * 32 + nf * 8]);
                mma_f16(gacc[nf], af, bf);
            }
        }
        __syncthreads();
    }

    {
        const int g2 = lane >> 2, q2 = lane & 3;
        float* gp = g_gram_part + ((size_t)blk * 8 + h) * 1024;
#pragma unroll
        for (int nf = 0; nf < 4; nf++) {
            int cb = nf * 8 + 2 * q2;
            *(float2*)&gp[(mi + g2) * 32 + cb] = make_float2(gacc[nf][0], gacc[nf][1]);
            *(float2*)&gp[(mi + g2 + 8) * 32 + cb] = make_float2(gacc[nf][2], gacc[nf][3]);
        }
    }

#pragma unroll
    for (int i = 0; i < 8; i++) {
#pragma unroll
        for (int off = 4; off <= 16; off <<= 1) {
            nq8[i] += __shfl_xor_sync(0xffffffffu, nq8[i], off);
            nk8[i] += __shfl_xor_sync(0xffffffffu, nk8[i], off);
        }
    }
    float* nsq = (float*)(smem + AH_OFF);
    float* nsk = nsq + 16 * 32;
    if (lane < 4) {
#pragma unroll
        for (int nf = 0; nf < 4; nf++) {
#pragma unroll
            for (int e = 0; e < 2; e++) {
                nsq[warp * 32 + nf * 8 + 2 * lane + e] = nq8[nf * 2 + e];
                nsk[warp * 32 + nf * 8 + 2 * lane + e] = nk8[nf * 2 + e];
            }
        }
    }
    __syncthreads();
    if (t < 256) {
        int j = t >> 5, loc = t & 31;
        g_ssq_part[(size_t)blk * 256 + t] = nsq[(2 * j) * 32 + loc] + nsq[(2 * j + 1) * 32 + loc];
        g_ssk_part[(size_t)blk * 256 + t] = nsk[(2 * j) * 32 + loc] + nsk[(2 * j + 1) * 32 + loc];
    }
}

// ================= v = f @ Wv (deep pipeline: 4-stage B, A reg-prefetch) =================
__global__ void __launch_bounds__(512) k_gemm_v(const float* __restrict__ f)
{
    __shared__ __half Ah[2][128 * SPH];
    __shared__ __half Bh[4][256 * SPH];

    const __half* Bt = g_Wt + 2 * 65536;
    __half* C = g_v;
    const int row0 = blockIdx.x * 128;

    const int t = threadIdx.x;
    const int warp = t >> 5, lane = t & 31;
    const int wm0 = (warp & 1) * 64, wn0 = (warp >> 1) * 32;
    const int g = lane >> 2, q = lane & 3;

    float acc[4][4][4];
#pragma unroll
    for (int mf = 0; mf < 4; mf++)
#pragma unroll
        for (int nf = 0; nf < 4; nf++)
#pragma unroll
            for (int r = 0; r < 4; r++) acc[mf][nf][r] = 0.f;

    const int ar = t >> 2, ak4 = (t & 3) * 4;
    const float* Ab = f + (size_t)(row0 + ar) * 256 + ak4;
    const int br = t >> 1, bk = (t & 1) * 8;
    const __half* Bb = Bt + (size_t)br * 256 + bk;

    cp16(&Bh[0][br * SPH + bk], Bb);
    CP_COMMIT();
    cp16(&Bh[1][br * SPH + bk], Bb + KC);
    CP_COMMIT();
    cp16(&Bh[2][br * SPH + bk], Bb + 2 * KC);
    CP_COMMIT();
    {
        float4 p0 = *(const float4*)(Ab);
        __half2 h[2];
        h[0] = __float22half2_rn(make_float2(p0.x, p0.y));
        h[1] = __float22half2_rn(make_float2(p0.z, p0.w));
        *(uint2*)&Ah[0][ar * SPH + ak4] = *(const uint2*)h;
    }
    float4 par0 = *(const float4*)(Ab + KC);
    float4 par1 = *(const float4*)(Ab + 2 * KC);

    for (int c = 0; c < 16; c++) {
        if (c <= 13)      { CP_WAIT(2); }
        else if (c == 14) { CP_WAIT(1); }
        else              { CP_WAIT(0); }
        __syncthreads();
        if (c < 15) {
            __half2 h[2];
            h[0] = __float22half2_rn(make_float2(par0.x, par0.y));
            h[1] = __float22half2_rn(make_float2(par0.z, par0.w));
            *(uint2*)&Ah[(c + 1) & 1][ar * SPH + ak4] = *(const uint2*)h;
            par0 = par1;
        }
        if (c + 3 < 16) {
            par1 = *(const float4*)(Ab + (c + 3) * KC);
            cp16(&Bh[(c + 3) & 3][br * SPH + bk], Bb + (c + 3) * KC);
            CP_COMMIT();
        }

        const __half* As = Ah[c & 1];
        const __half* Bs = Bh[c & 3];

        uint32_t bf[4][2];
#pragma unroll
        for (int nf = 0; nf < 4; nf++) {
            int n = wn0 + nf * 8 + g;
            bf[nf][0] = *(const uint32_t*)&Bs[n * SPH + 2 * q];
            bf[nf][1] = *(const uint32_t*)&Bs[n * SPH + 2 * q + 8];
        }
#pragma unroll
        for (int mf = 0; mf < 4; mf++) {
            int r = wm0 + mf * 16 + g;
            uint32_t af[4];
            af[0] = *(const uint32_t*)&As[r * SPH + 2 * q];
            af[1] = *(const uint32_t*)&As[(r + 8) * SPH + 2 * q];
            af[2] = *(const uint32_t*)&As[r * SPH + 2 * q + 8];
            af[3] = *(const uint32_t*)&As[(r + 8) * SPH + 2 * q + 8];
#pragma unroll
            for (int nf = 0; nf < 4; nf++)
                mma_f16(acc[mf][nf], af, bf[nf]);
        }
    }

#pragma unroll
    for (int mf = 0; mf < 4; mf++) {
        int rbase = row0 + wm0 + mf * 16 + g;
#pragma unroll
        for (int nf = 0; nf < 4; nf++) {
            int cb = wn0 + nf * 8 + 2 * q;
            *(__half2*)(C + (size_t)rbase * 256 + cb)
                = __float22half2_rn(make_float2(acc[mf][nf][0], acc[mf][nf][1]));
            *(__half2*)(C + (size_t)(rbase + 8) * 256 + cb)
                = __float22half2_rn(make_float2(acc[mf][nf][2], acc[mf][nf][3]));
        }
    }
}

// ---- OUT: A fp16 + B fp16, both 4-stage cp.async; accumulate into f32 d_out ----
__global__ void __launch_bounds__(512) k_gemm_out(
    const float* __restrict__ bp, float* __restrict__ out)
{
    __shared__ __half As4[4][128 * SPH];
    __shared__ __half Bs4[4][256 * SPH];

    const int row0 = blockIdx.x * 128;
    const int b = row0 >> 14;
    const __half* Bt = g_Mt + (size_t)b * 65536;

    const int t = threadIdx.x;
    const int warp = t >> 5, lane = t & 31;
    const int wm0 = (warp & 1) * 64, wn0 = (warp >> 1) * 32;
    const int g = lane >> 2, q = lane & 3;

    float acc[4][4][4];
#pragma unroll
    for (int mf = 0; mf < 4; mf++)
#pragma unroll
        for (int nf = 0; nf < 4; nf++)
#pragma unroll
            for (int r = 0; r < 4; r++) acc[mf][nf][r] = 0.f;

    const int ar = t >> 1, ak = (t & 1) * 8;
    const __half* Ab = g_v + (size_t)(row0 + ar) * 256 + ak;
    const __half* Bb = Bt + (size_t)ar * 256 + ak;

#pragma unroll
    for (int pc = 0; pc < 3; pc++) {
        if (t < 256) cp16(&As4[pc][ar * SPH + ak], Ab + pc * KC);
        cp16(&Bs4[pc][ar * SPH + ak], Bb + pc * KC);
        CP_COMMIT();
    }

    for (int c = 0; c < 16; c++) {
        if (c <= 13)      { CP_WAIT(2); }
        else if (c == 14) { CP_WAIT(1); }
        else              { CP_WAIT(0); }
        __syncthreads();
        if (c + 3 < 16) {
            if (t < 256) cp16(&As4[(c + 3) & 3][ar * SPH + ak], Ab + (c + 3) * KC);
            cp16(&Bs4[(c + 3) & 3][ar * SPH + ak], Bb + (c + 3) * KC);
            CP_COMMIT();
        }
        const __half* As = As4[c & 3];
        const __half* Bs = Bs4[c & 3];

        uint32_t bf[4][2];
#pragma unroll
        for (int nf = 0; nf < 4; nf++) {
            int n = wn0 + nf * 8 + g;
            bf[nf][0] = *(const uint32_t*)&Bs[n * SPH + 2 * q];
            bf[nf][1] = *(const uint32_t*)&Bs[n * SPH + 2 * q + 8];
        }
#pragma unroll
        for (int mf = 0; mf < 4; mf++) {
            int r = wm0 + mf * 16 + g;
            uint32_t af[4];
            af[0] = *(const uint32_t*)&As[r * SPH + 2 * q];
            af[1] = *(const uint32_t*)&As[(r + 8) * SPH + 2 * q];
            af[2] = *(const uint32_t*)&As[r * SPH + 2 * q + 8];
            af[3] = *(const uint32_t*)&As[(r + 8) * SPH + 2 * q + 8];
#pragma unroll
            for (int nf = 0; nf < 4; nf++)
                mma_f16(acc[mf][nf], af, bf[nf]);
        }
    }

#pragma unroll
    for (int mf = 0; mf < 4; mf++) {
        int rbase = row0 + wm0 + mf * 16 + g;
#pragma unroll
        for (int nf = 0; nf < 4; nf++) {
            int cb = wn0 + nf * 8 + 2 * q;
            float2 bb = *(const float2*)(bp + cb);
            float2* p0 = (float2*)(out + (size_t)rbase * 256 + cb);
            float2* p1 = (float2*)(out + (size_t)(rbase + 8) * 256 + cb);
            float2 o0 = *p0, o1 = *p1;
            o0.x += acc[mf][nf][0] + bb.x; o0.y += acc[mf][nf][1] + bb.y;
            o1.x += acc[mf][nf][2] + bb.x; o1.y += acc[mf][nf][3] + bb.y;
            *p0 = o0;
            *p1 = o1;
        }
    }
}

// =================== weight transpose + fp16 conversion ===================
__global__ void k_wt(const float* __restrict__ Wq, const float* __restrict__ Wk,
                     const float* __restrict__ Wv)
{
    int z = blockIdx.z;
    const float* W = (z == 0) ? Wq : (z == 1) ? Wk : Wv;
    __half* Wt = g_Wt + (size_t)z * 65536;
    __shared__ float tile[32][33];
    int tx = threadIdx.x, ty = threadIdx.y;
    int k0 = blockIdx.y * 32, n0 = blockIdx.x * 32;
#pragma unroll
    for (int i = 0; i < 4; i++)
        tile[ty + 8 * i][tx] = W[(size_t)(k0 + ty + 8 * i) * 256 + n0 + tx];
    __syncthreads();
#pragma unroll
    for (int i = 0; i < 4; i++)
        Wt[(size_t)(n0 + ty + 8 * i) * 256 + k0 + tx] = __float2half_rn(tile[tx][ty + 8 * i]);
}

// ============ norms + G + softmax + fold into Wp -> Mt ============
__global__ void k_attn_m(const float* __restrict__ Wp, const float* __restrict__ rescale)
{
    int bh = blockIdx.x, b = bh >> 3, h = bh & 7;
    int t = threadIdx.x;
    __shared__ float attn[32][32];
    __shared__ float wp[32][256];
    __shared__ float nq[32], nk[32];

#pragma unroll
    for (int s = 0; s < 32; s++) {
        int idx = t + s * 256;
        wp[idx >> 8][idx & 255] = Wp[(size_t)(h * 32 + (idx >> 8)) * 256 + (idx & 255)];
    }
    if (t < 32) {
        float sq = 0.f, sk = 0.f;
#pragma unroll
        for (int ch = 0; ch < 32; ch++) {
            sq += g_ssq_part[(size_t)(b * 32 + ch) * 256 + h * 32 + t];
            sk += g_ssk_part[(size_t)(b * 32 + ch) * 256 + h * 32 + t];
        }
        nq[t] = fmaxf(sqrtf(sq), 1e-12f);
        nk[t] = fmaxf(sqrtf(sk), 1e-12f);
    }
    __syncthreads();

    float resc = rescale[h];
    int w = t >> 5, lane = t & 31;
    for (int i = w; i < 32; i += 8) {
        float g = 0.f;
#pragma unroll
        for (int ch = 0; ch < 32; ch++)
            g += g_gram_part[((size_t)(b * 32 + ch) * 8 + h) * 1024 + i * 32 + lane];
        float val = g / (nk[i] * nq[lane]) * resc;
        float m = val;
#pragma unroll
        for (int o = 16; o; o >>= 1) m = fmaxf(m, __shfl_xor_sync(0xffffffffu, m, o));
        float e = expf(val - m);
        float ssum = e;
#pragma unroll
        for (int o = 16; o; o >>= 1) ssum += __shfl_xor_sync(0xffffffffu, ssum, o);
        attn[i][lane] = e / ssum;
    }
    __syncthreads();

    float acc[32];
#pragma unroll
    for (int j = 0; j < 32; j++) acc[j] = 0.f;
#pragma unroll 4
    for (int i = 0; i < 32; i++) {
        float wpv = wp[i][t];
#pragma unroll
        for (int j = 0; j < 32; j++) acc[j] += attn[i][j] * wpv;
    }
#pragma unroll
    for (int j = 0; j < 32; j++)
        g_Mt[((size_t)b * 256 + t) * 256 + h * 32 + j] = __float2half_rn(acc[j]);
}

// =================== fused positional branch (reads fp16 v) ===================
__device__ __forceinline__ float gelu_exact(float x)
{
    return 0.5f * x * (1.0f + erff(x * 0.7071067811865475f));
}

__global__ void __launch_bounds__(256) k_conv(
    const float* __restrict__ pw1, const float* __restrict__ pw2,
    float* __restrict__ out)
{
    __shared__ float vs[20][20][16];
    __shared__ float t1[18][18][16];
    const int t = threadIdx.x;
    const int cl = t & 15;
    const int tp = t >> 4;
    const int c = (blockIdx.y << 4) + cl;
    const int tx0 = (blockIdx.x & 7) * 16, ty0 = (blockIdx.x >> 3) * 16;
    const int b = blockIdx.z;

    float w1[9], w2[9];
#pragma unroll
    for (int i = 0; i < 9; i++) {
        w1[i] = pw1[i * 256 + c];
        w2[i] = pw2[i * 256 + c];
    }

    for (int p = tp; p < 400; p += 16) {
        int py = p / 20, px = p - py * 20;
        int gy = ty0 + py - 2, gx = tx0 + px - 2;
        float v = 0.f;
        if (gy >= 0 && gy < 128 && gx >= 0 && gx < 128)
            v = __half2float(g_v[(((size_t)(b * 128 + gy)) * 128 + gx) * 256 + c]);
        vs[py][px][cl] = v;
    }
    __syncthreads();

    for (int p = tp; p < 324; p += 16) {
        int py = p / 18, px = p - py * 18;
        float acc = 0.f;
#pragma unroll
        for (int dy = 0; dy < 3; dy++)
#pragma unroll
            for (int dx = 0; dx < 3; dx++)
                acc += vs[py + dy][px + dx][cl] * w1[dy * 3 + dx];
        int gy = ty0 + py - 1, gx = tx0 + px - 1;
        float val = (gy >= 0 && gy < 128 && gx >= 0 && gx < 128) ? gelu_exact(acc) : 0.f;
        t1[py][px][cl] = val;
    }
    __syncthreads();

    for (int p = tp; p < 256; p += 16) {
        int py = p >> 4, px = p & 15;
        float acc = 0.f;
#pragma unroll
        for (int dy = 0; dy < 3; dy++)
#pragma unroll
            for (int dx = 0; dx < 3; dx++)
                acc += t1[py + dy][px + dx][cl] * w2[dy * 3 + dx];
        out[(((size_t)(b * 128 + ty0 + py)) * 128 + tx0 + px) * 256 + c] = acc;
    }
}

extern "C" void kernel_launch(void* const* d_in, const int* in_sizes, int n_in,
                              void* d_out, int out_size)
{
    const float* x_in    = (const float*)d_in[0];
    const float* y_in    = (const float*)d_in[1];
    const float* f_in    = (const float*)d_in[2];
    const float* Wq      = (const float*)d_in[3];
    const float* Wk      = (const float*)d_in[4];
    const float* Wv      = (const float*)d_in[5];
    const float* rescale = (const float*)d_in[6];
    const float* Wp      = (const float*)d_in[7];
    const float* bp      = (const float*)d_in[8];
    const float* pw1     = (const float*)d_in[9];
    const float* pw2     = (const float*)d_in[10];
    float* out = (float*)d_out;

    cudaFuncSetAttribute(k_qkgram, cudaFuncAttributeMaxDynamicSharedMemorySize, QKG_SMEM);

    // 1) transpose + fp16-convert weights
    k_wt<<<dim3(8, 8, 3), dim3(32, 8)>>>(Wq, Wk, Wv);
    // 2) v = f @ Wv (deep pipeline)
    k_gemm_v<<<512, 512>>>(f_in);
    // 3) positional branch writes d_out
    k_conv<<<dim3(64, 16, 4), 256>>>(pw1, pw2, out);
    // 4) fused Q/K projection + Gram + norms
    k_qkgram<<<128, 512, QKG_SMEM>>>(x_in, y_in);
    // 5) softmax + fold attention into Wp -> per-batch Mt (fp16)
    k_attn_m<<<32, 256>>>(Wp, rescale);
    // 6) out += v @ M[b] + bp (deep pipeline)
    k_gemm_out<<<512, 512>>>(bp, out);
}

// round 13
// speedup vs baseline: 1.5180x; 1.0494x over previous
#include <cuda_runtime.h>
#include <cuda_fp16.h>
#include <math.h>
#include <stdint.h>

#define B_    4
#define NTOK  16384
#define C_    256
#define BN_   65536
#define NQB   256                 // qkgram blocks (256 tokens each)
#define CPB   64                  // chunks per batch = NQB / B_

// ---------------- static device scratch ----------------
__device__ __half g_v[BN_ * C_];
__device__ __half g_Wt[3 * C_ * C_];
__device__ __half g_Mt[B_ * C_ * C_];
__device__ float g_gram_part[NQB * 8 * 32 * 32];   // 8 MB [blk][h][i][j]
__device__ float g_ssq_part[NQB * C_];
__device__ float g_ssk_part[NQB * C_];

__device__ __forceinline__ void mma_f16(float* c, const uint32_t* a, const uint32_t* b) {
    asm volatile(
        "mma.sync.aligned.m16n8k16.row.col.f32.f16.f16.f32 "
        "{%0,%1,%2,%3}, {%4,%5,%6,%7}, {%8,%9}, {%0,%1,%2,%3};"
        : "+f"(c[0]), "+f"(c[1]), "+f"(c[2]), "+f"(c[3])
        : "r"(a[0]), "r"(a[1]), "r"(a[2]), "r"(a[3]), "r"(b[0]), "r"(b[1]));
}
__device__ __forceinline__ void cp16(void* s, const void* g) {
    uint32_t sa = (uint32_t)__cvta_generic_to_shared(s);
    asm volatile("cp.async.cg.shared.global [%0], [%1], 16;" :: "r"(sa), "l"(g));
}
#define CP_COMMIT() asm volatile("cp.async.commit_group;" ::: "memory")
#define CP_WAIT(n)  asm volatile("cp.async.wait_group %0;" :: "n"(n) : "memory")

__device__ __forceinline__ void ldsm4t(uint32_t* r, const __half* p) {
    uint32_t a = (uint32_t)__cvta_generic_to_shared(p);
    asm volatile("ldmatrix.sync.aligned.m8n8.x4.trans.shared.b16 {%0,%1,%2,%3}, [%4];"
                 : "=r"(r[0]), "=r"(r[1]), "=r"(r[2]), "=r"(r[3]) : "r"(a));
}
__device__ __forceinline__ void ldsm2t(uint32_t* r, const __half* p) {
    uint32_t a = (uint32_t)__cvta_generic_to_shared(p);
    asm volatile("ldmatrix.sync.aligned.m8n8.x2.trans.shared.b16 {%0,%1}, [%2];"
                 : "=r"(r[0]), "=r"(r[1]) : "r"(a));
}

#define KC   16
#define SPH  24
#define RS   264

// ---- qkgram smem layout (within dynamic smem) ----
#define KT_OFF  (128 * RS)                       // halves
#define AH_OFF  (2 * 128 * RS * 2)               // bytes: 135168
#define BH_OFF  (AH_OFF + 2 * 128 * SPH * 2)     // +12288 = 147456
#define QKG_SMEM (BH_OFF + 4 * 256 * SPH * 2)    // +49152 = 196608

// projection pass: tile[128x256 fp16 smem] = A[128x256 fp32] @ Bt^T
__device__ __forceinline__ void proj_pass(
    const float* __restrict__ Asrc, const __half* __restrict__ Bt,
    __half* tile, __half* Ah, __half* Bh, int t, float* nacc)
{
    const int warp = t >> 5, lane = t & 31;
    const int wm0 = (warp & 1) * 64, wn0 = (warp >> 1) * 32;
    const int g = lane >> 2, q = lane & 3;
    const int ar = t >> 2, ak4 = (t & 3) * 4;
    const int br = t >> 1, bk = (t & 1) * 8;
    const float* Ab = Asrc + (size_t)ar * 256 + ak4;
    const __half* Bb = Bt + (size_t)br * 256 + bk;

    float acc[4][4][4];
#pragma unroll
    for (int mf = 0; mf < 4; mf++)
#pragma unroll
        for (int nf = 0; nf < 4; nf++)
#pragma unroll
            for (int r = 0; r < 4; r++) acc[mf][nf][r] = 0.f;

    cp16(Bh + 0 * (256 * SPH) + br * SPH + bk, Bb);
    CP_COMMIT();
    cp16(Bh + 1 * (256 * SPH) + br * SPH + bk, Bb + KC);
    CP_COMMIT();
    cp16(Bh + 2 * (256 * SPH) + br * SPH + bk, Bb + 2 * KC);
    CP_COMMIT();
    {
        float4 p0 = *(const float4*)(Ab);
        __half2 h[2];
        h[0] = __float22half2_rn(make_float2(p0.x, p0.y));
        h[1] = __float22half2_rn(make_float2(p0.z, p0.w));
        *(uint2*)&Ah[ar * SPH + ak4] = *(const uint2*)h;
    }
    float4 par0 = *(const float4*)(Ab + KC);
    float4 par1 = *(const float4*)(Ab + 2 * KC);

    for (int c = 0; c < 16; c++) {
        if (c <= 13)      { CP_WAIT(2); }
        else if (c == 14) { CP_WAIT(1); }
        else              { CP_WAIT(0); }
        __syncthreads();
        if (c < 15) {
            __half2 h[2];
            h[0] = __float22half2_rn(make_float2(par0.x, par0.y));
            h[1] = __float22half2_rn(make_float2(par0.z, par0.w));
            *(uint2*)&Ah[((c + 1) & 1) * (128 * SPH) + ar * SPH + ak4] = *(const uint2*)h;
            par0 = par1;
        }
        if (c + 3 < 16) {
            par1 = *(const float4*)(Ab + (c + 3) * KC);
            cp16(Bh + ((c + 3) & 3) * (256 * SPH) + br * SPH + bk, Bb + (c + 3) * KC);
            CP_COMMIT();
        }

        const __half* As = Ah + (c & 1) * (128 * SPH);
        const __half* Bs = Bh + (c & 3) * (256 * SPH);

        uint32_t bf[4][2];
#pragma unroll
        for (int nf = 0; nf < 4; nf++) {
            int n = wn0 + nf * 8 + g;
            bf[nf][0] = *(const uint32_t*)&Bs[n * SPH + 2 * q];
            bf[nf][1] = *(const uint32_t*)&Bs[n * SPH + 2 * q + 8];
        }
#pragma unroll
        for (int mf = 0; mf < 4; mf++) {
            int r = wm0 + mf * 16 + g;
            uint32_t af[4];
            af[0] = *(const uint32_t*)&As[r * SPH + 2 * q];
            af[1] = *(const uint32_t*)&As[(r + 8) * SPH + 2 * q];
            af[2] = *(const uint32_t*)&As[r * SPH + 2 * q + 8];
            af[3] = *(const uint32_t*)&As[(r + 8) * SPH + 2 * q + 8];
#pragma unroll
            for (int nf = 0; nf < 4; nf++)
                mma_f16(acc[mf][nf], af, bf[nf]);
        }
    }

#pragma unroll
    for (int mf = 0; mf < 4; mf++) {
        int r = wm0 + mf * 16 + g;
#pragma unroll
        for (int nf = 0; nf < 4; nf++) {
            int cb = wn0 + nf * 8 + 2 * q;
            __half2 h2a = __float22half2_rn(make_float2(acc[mf][nf][0], acc[mf][nf][1]));
            __half2 h2b = __float22half2_rn(make_float2(acc[mf][nf][2], acc[mf][nf][3]));
            *(__half2*)&tile[r * RS + cb] = h2a;
            *(__half2*)&tile[(r + 8) * RS + cb] = h2b;
            float2 fa = __half22float2(h2a), fb = __half22float2(h2b);
            nacc[nf * 2 + 0] += fa.x * fa.x + fb.x * fb.x;
            nacc[nf * 2 + 1] += fa.y * fa.y + fb.y * fb.y;
        }
    }
}

// ---------------- qkgram body: 256 tokens per block ----------------
__device__ __forceinline__ void qkgram_body(
    char* smem, int blk, const float* __restrict__ x, const float* __restrict__ y)
{
    __half* qtile = (__half*)smem;
    __half* ktile = qtile + KT_OFF;
    __half* Ah = (__half*)(smem + AH_OFF);
    __half* Bh = (__half*)(smem + BH_OFF);

    const size_t tokbase = (size_t)blk * 256;
    const int t = threadIdx.x;
    const int warp = t >> 5, lane = t & 31;

    const int h = warp >> 1, mi = (warp & 1) * 16;
    const int lrowA = (lane & 7) + ((lane >> 4) << 3);
    const int lcolA = ((lane >> 3) & 1) << 3;
    const int lrowB = (lane & 7) + (((lane >> 3) & 1) << 3);
    float gacc[4][4];
#pragma unroll
    for (int nf = 0; nf < 4; nf++)
#pragma unroll
        for (int r = 0; r < 4; r++) gacc[nf][r] = 0.f;

    float nq8[8], nk8[8];
#pragma unroll
    for (int i = 0; i < 8; i++) { nq8[i] = 0.f; nk8[i] = 0.f; }

    for (int s = 0; s < 2; s++) {
        const size_t tb = (tokbase + s * 128) * 256;
        proj_pass(x + tb, g_Wt, qtile, Ah, Bh, t, nq8);
        proj_pass(y + tb, g_Wt + 65536, ktile, Ah, Bh, t, nk8);
        __syncthreads();

#pragma unroll
        for (int k0 = 0; k0 < 128; k0 += 16) {
            uint32_t af[4];
            ldsm4t(af, &ktile[(k0 + lrowA) * RS + h * 32 + mi + lcolA]);
#pragma unroll
            for (int nf = 0; nf < 4; nf++) {
                uint32_t bf[2];
                ldsm2t(bf, &qtile[(k0 + lrowB) * RS + h * 32 + nf * 8]);
                mma_f16(gacc[nf], af, bf);
            }
        }
        __syncthreads();
    }

    {
        const int g2 = lane >> 2, q2 = lane & 3;
        float* gp = g_gram_part + ((size_t)blk * 8 + h) * 1024;
#pragma unroll
        for (int nf = 0; nf < 4; nf++) {
            int cb = nf * 8 + 2 * q2;
            *(float2*)&gp[(mi + g2) * 32 + cb] = make_float2(gacc[nf][0], gacc[nf][1]);
            *(float2*)&gp[(mi + g2 + 8) * 32 + cb] = make_float2(gacc[nf][2], gacc[nf][3]);
        }
    }

#pragma unroll
    for (int i = 0; i < 8; i++) {
#pragma unroll
        for (int off = 4; off <= 16; off <<= 1) {
            nq8[i] += __shfl_xor_sync(0xffffffffu, nq8[i], off);
            nk8[i] += __shfl_xor_sync(0xffffffffu, nk8[i], off);
        }
    }
    float* nsq = (float*)(smem + AH_OFF);
    float* nsk = nsq + 16 * 32;
    if (lane < 4) {
#pragma unroll
        for (int nf = 0; nf < 4; nf++) {
#pragma unroll
            for (int e = 0; e < 2; e++) {
                nsq[warp * 32 + nf * 8 + 2 * lane + e] = nq8[nf * 2 + e];
                nsk[warp * 32 + nf * 8 + 2 * lane + e] = nk8[nf * 2 + e];
            }
        }
    }
    __syncthreads();
    if (t < 256) {
        int j = t >> 5, loc = t & 31;
        g_ssq_part[(size_t)blk * 256 + t] = nsq[(2 * j) * 32 + loc] + nsq[(2 * j + 1) * 32 + loc];
        g_ssk_part[(size_t)blk * 256 + t] = nsk[(2 * j) * 32 + loc] + nsk[(2 * j + 1) * 32 + loc];
    }
}

// ---------------- gemm_v body (deep pipeline, dynamic smem) ----------------
__device__ __forceinline__ void gemmv_body(char* smem, int vblk, const float* __restrict__ f)
{
    __half* Ah = (__half*)smem;                         // [2][128*SPH]
    __half* Bh = (__half*)(smem + 2 * 128 * SPH * 2);   // [4][256*SPH]

    const __half* Bt = g_Wt + 2 * 65536;
    __half* C = g_v;
    const int row0 = vblk * 128;

    const int t = threadIdx.x;
    const int warp = t >> 5, lane = t & 31;
    const int wm0 = (warp & 1) * 64, wn0 = (warp >> 1) * 32;
    const int g = lane >> 2, q = lane & 3;

    float acc[4][4][4];
#pragma unroll
    for (int mf = 0; mf < 4; mf++)
#pragma unroll
        for (int nf = 0; nf < 4; nf++)
#pragma unroll
            for (int r = 0; r < 4; r++) acc[mf][nf][r] = 0.f;

    const int ar = t >> 2, ak4 = (t & 3) * 4;
    const float* Ab = f + (size_t)(row0 + ar) * 256 + ak4;
    const int br = t >> 1, bk = (t & 1) * 8;
    const __half* Bb = Bt + (size_t)br * 256 + bk;

    cp16(Bh + 0 * (256 * SPH) + br * SPH + bk, Bb);
    CP_COMMIT();
    cp16(Bh + 1 * (256 * SPH) + br * SPH + bk, Bb + KC);
    CP_COMMIT();
    cp16(Bh + 2 * (256 * SPH) + br * SPH + bk, Bb + 2 * KC);
    CP_COMMIT();
    {
        float4 p0 = *(const float4*)(Ab);
        __half2 h[2];
        h[0] = __float22half2_rn(make_float2(p0.x, p0.y));
        h[1] = __float22half2_rn(make_float2(p0.z, p0.w));
        *(uint2*)&Ah[ar * SPH + ak4] = *(const uint2*)h;
    }
    float4 par0 = *(const float4*)(Ab + KC);
    float4 par1 = *(const float4*)(Ab + 2 * KC);

    for (int c = 0; c < 16; c++) {
        if (c <= 13)      { CP_WAIT(2); }
        else if (c == 14) { CP_WAIT(1); }
        else              { CP_WAIT(0); }
        __syncthreads();
        if (c < 15) {
            __half2 h[2];
            h[0] = __float22half2_rn(make_float2(par0.x, par0.y));
            h[1] = __float22half2_rn(make_float2(par0.z, par0.w));
            *(uint2*)&Ah[((c + 1) & 1) * (128 * SPH) + ar * SPH + ak4] = *(const uint2*)h;
            par0 = par1;
        }
        if (c + 3 < 16) {
            par1 = *(const float4*)(Ab + (c + 3) * KC);
            cp16(Bh + ((c + 3) & 3) * (256 * SPH) + br * SPH + bk, Bb + (c + 3) * KC);
            CP_COMMIT();
        }

        const __half* As = Ah + (c & 1) * (128 * SPH);
        const __half* Bs = Bh + (c & 3) * (256 * SPH);

        uint32_t bf[4][2];
#pragma unroll
        for (int nf = 0; nf < 4; nf++) {
            int n = wn0 + nf * 8 + g;
            bf[nf][0] = *(const uint32_t*)&Bs[n * SPH + 2 * q];
            bf[nf][1] = *(const uint32_t*)&Bs[n * SPH + 2 * q + 8];
        }
#pragma unroll
        for (int mf = 0; mf < 4; mf++) {
            int r = wm0 + mf * 16 + g;
            uint32_t af[4];
            af[0] = *(const uint32_t*)&As[r * SPH + 2 * q];
            af[1] = *(const uint32_t*)&As[(r + 8) * SPH + 2 * q];
            af[2] = *(const uint32_t*)&As[r * SPH + 2 * q + 8];
            af[3] = *(const uint32_t*)&As[(r + 8) * SPH + 2 * q + 8];
#pragma unroll
            for (int nf = 0; nf < 4; nf++)
                mma_f16(acc[mf][nf], af, bf[nf]);
        }
    }

#pragma unroll
    for (int mf = 0; mf < 4; mf++) {
        int rbase = row0 + wm0 + mf * 16 + g;
#pragma unroll
        for (int nf = 0; nf < 4; nf++) {
            int cb = wn0 + nf * 8 + 2 * q;
            *(__half2*)(C + (size_t)rbase * 256 + cb)
                = __float22half2_rn(make_float2(acc[mf][nf][0], acc[mf][nf][1]));
            *(__half2*)(C + (size_t)(rbase + 8) * 256 + cb)
                = __float22half2_rn(make_float2(acc[mf][nf][2], acc[mf][nf][3]));
        }
    }
}

// ================= fused launch: qkgram blocks then gemm_v blocks =================
__global__ void __launch_bounds__(512) k_fused(
    const float* __restrict__ x, const float* __restrict__ y, const float* __restrict__ f)
{
    extern __shared__ char smem[];
    if (blockIdx.x < NQB) qkgram_body(smem, blockIdx.x, x, y);
    else                  gemmv_body(smem, blockIdx.x - NQB, f);
}

// ---- OUT: A fp16 + B fp16, both 4-stage cp.async; accumulate into f32 d_out ----
__global__ void __launch_bounds__(512) k_gemm_out(
    const float* __restrict__ bp, float* __restrict__ out)
{
    __shared__ __half As4[4][128 * SPH];
    __shared__ __half Bs4[4][256 * SPH];

    const int row0 = blockIdx.x * 128;
    const int b = row0 >> 14;
    const __half* Bt = g_Mt + (size_t)b * 65536;

    const int t = threadIdx.x;
    const int warp = t >> 5, lane = t & 31;
    const int wm0 = (warp & 1) * 64, wn0 = (warp >> 1) * 32;
    const int g = lane >> 2, q = lane & 3;

    float acc[4][4][4];
#pragma unroll
    for (int mf = 0; mf < 4; mf++)
#pragma unroll
        for (int nf = 0; nf < 4; nf++)
#pragma unroll
            for (int r = 0; r < 4; r++) acc[mf][nf][r] = 0.f;

    const int ar = t >> 1, ak = (t & 1) * 8;
    const __half* Ab = g_v + (size_t)(row0 + ar) * 256 + ak;
    const __half* Bb = Bt + (size_t)ar * 256 + ak;

#pragma unroll
    for (int pc = 0; pc < 3; pc++) {
        if (t < 256) cp16(&As4[pc][ar * SPH + ak], Ab + pc * KC);
        cp16(&Bs4[pc][ar * SPH + ak], Bb + pc * KC);
        CP_COMMIT();
    }

    for (int c = 0; c < 16; c++) {
        if (c <= 13)      { CP_WAIT(2); }
        else if (c == 14) { CP_WAIT(1); }
        else              { CP_WAIT(0); }
        __syncthreads();
        if (c + 3 < 16) {
            if (t < 256) cp16(&As4[(c + 3) & 3][ar * SPH + ak], Ab + (c + 3) * KC);
            cp16(&Bs4[(c + 3) & 3][ar * SPH + ak], Bb + (c + 3) * KC);
            CP_COMMIT();
        }
        const __half* As = As4[c & 3];
        const __half* Bs = Bs4[c & 3];

        uint32_t bf[4][2];
#pragma unroll
        for (int nf = 0; nf < 4; nf++) {
            int n = wn0 + nf * 8 + g;
            bf[nf][0] = *(const uint32_t*)&Bs[n * SPH + 2 * q];
            bf[nf][1] = *(const uint32_t*)&Bs[n * SPH + 2 * q + 8];
        }
#pragma unroll
        for (int mf = 0; mf < 4; mf++) {
            int r = wm0 + mf * 16 + g;
            uint32_t af[4];
            af[0] = *(const uint32_t*)&As[r * SPH + 2 * q];
            af[1] = *(const uint32_t*)&As[(r + 8) * SPH + 2 * q];
            af[2] = *(const uint32_t*)&As[r * SPH + 2 * q + 8];
            af[3] = *(const uint32_t*)&As[(r + 8) * SPH + 2 * q + 8];
#pragma unroll
            for (int nf = 0; nf < 4; nf++)
                mma_f16(acc[mf][nf], af, bf[nf]);
        }
    }

#pragma unroll
    for (int mf = 0; mf < 4; mf++) {
        int rbase = row0 + wm0 + mf * 16 + g;
#pragma unroll
        for (int nf = 0; nf < 4; nf++) {
            int cb = wn0 + nf * 8 + 2 * q;
            float2 bb = *(const float2*)(bp + cb);
            float2* p0 = (float2*)(out + (size_t)rbase * 256 + cb);
            float2* p1 = (float2*)(out + (size_t)(rbase + 8) * 256 + cb);
            float2 o0 = *p0, o1 = *p1;
            o0.x += acc[mf][nf][0] + bb.x; o0.y += acc[mf][nf][1] + bb.y;
            o1.x += acc[mf][nf][2] + bb.x; o1.y += acc[mf][nf][3] + bb.y;
            *p0 = o0;
            *p1 = o1;
        }
    }
}

// =================== weight transpose + fp16 conversion ===================
__global__ void k_wt(const float* __restrict__ Wq, const float* __restrict__ Wk,
                     const float* __restrict__ Wv)
{
    int z = blockIdx.z;
    const float* W = (z == 0) ? Wq : (z == 1) ? Wk : Wv;
    __half* Wt = g_Wt + (size_t)z * 65536;
    __shared__ float tile[32][33];
    int tx = threadIdx.x, ty = threadIdx.y;
    int k0 = blockIdx.y * 32, n0 = blockIdx.x * 32;
#pragma unroll
    for (int i = 0; i < 4; i++)
        tile[ty + 8 * i][tx] = W[(size_t)(k0 + ty + 8 * i) * 256 + n0 + tx];
    __syncthreads();
#pragma unroll
    for (int i = 0; i < 4; i++)
        Wt[(size_t)(n0 + ty + 8 * i) * 256 + k0 + tx] = __float2half_rn(tile[tx][ty + 8 * i]);
}

// ============ norms + G + softmax + fold into Wp -> Mt (CPB chunks) ============
__global__ void k_attn_m(const float* __restrict__ Wp, const float* __restrict__ rescale)
{
    int bh = blockIdx.x, b = bh >> 3, h = bh & 7;
    int t = threadIdx.x;
    __shared__ float attn[32][32];
    __shared__ float wp[32][256];
    __shared__ float nq[32], nk[32];

#pragma unroll
    for (int s = 0; s < 32; s++) {
        int idx = t + s * 256;
        wp[idx >> 8][idx & 255] = Wp[(size_t)(h * 32 + (idx >> 8)) * 256 + (idx & 255)];
    }
    if (t < 32) {
        float sq = 0.f, sk = 0.f;
#pragma unroll
        for (int ch = 0; ch < CPB; ch++) {
            sq += g_ssq_part[(size_t)(b * CPB + ch) * 256 + h * 32 + t];
            sk += g_ssk_part[(size_t)(b * CPB + ch) * 256 + h * 32 + t];
        }
        nq[t] = fmaxf(sqrtf(sq), 1e-12f);
        nk[t] = fmaxf(sqrtf(sk), 1e-12f);
    }
    __syncthreads();

    float resc = rescale[h];
    int w = t >> 5, lane = t & 31;
    for (int i = w; i < 32; i += 8) {
        float g = 0.f;
#pragma unroll
        for (int ch = 0; ch < CPB; ch++)
            g += g_gram_part[((size_t)(b * CPB + ch) * 8 + h) * 1024 + i * 32 + lane];
        float val = g / (nk[i] * nq[lane]) * resc;
        float m = val;
#pragma unroll
        for (int o = 16; o; o >>= 1) m = fmaxf(m, __shfl_xor_sync(0xffffffffu, m, o));
        float e = expf(val - m);
        float ssum = e;
#pragma unroll
        for (int o = 16; o; o >>= 1) ssum += __shfl_xor_sync(0xffffffffu, ssum, o);
        attn[i][lane] = e / ssum;
    }
    __syncthreads();

    float acc[32];
#pragma unroll
    for (int j = 0; j < 32; j++) acc[j] = 0.f;
#pragma unroll 4
    for (int i = 0; i < 32; i++) {
        float wpv = wp[i][t];
#pragma unroll
        for (int j = 0; j < 32; j++) acc[j] += attn[i][j] * wpv;
    }
#pragma unroll
    for (int j = 0; j < 32; j++)
        g_Mt[((size_t)b * 256 + t) * 256 + h * 32 + j] = __float2half_rn(acc[j]);
}

// =================== fused positional branch (reads fp16 v) ===================
__device__ __forceinline__ float gelu_exact(float x)
{
    return 0.5f * x * (1.0f + erff(x * 0.7071067811865475f));
}

__global__ void __launch_bounds__(256) k_conv(
    const float* __restrict__ pw1, const float* __restrict__ pw2,
    float* __restrict__ out)
{
    __shared__ float vs[20][20][16];
    __shared__ float t1[18][18][16];
    const int t = threadIdx.x;
    const int cl = t & 15;
    const int tp = t >> 4;
    const int c = (blockIdx.y << 4) + cl;
    const int tx0 = (blockIdx.x & 7) * 16, ty0 = (blockIdx.x >> 3) * 16;
    const int b = blockIdx.z;

    float w1[9], w2[9];
#pragma unroll
    for (int i = 0; i < 9; i++) {
        w1[i] = pw1[i * 256 + c];
        w2[i] = pw2[i * 256 + c];
    }

    for (int p = tp; p < 400; p += 16) {
        int py = p / 20, px = p - py * 20;
        int gy = ty0 + py - 2, gx = tx0 + px - 2;
        float v = 0.f;
        if (gy >= 0 && gy < 128 && gx >= 0 && gx < 128)
            v = __half2float(g_v[(((size_t)(b * 128 + gy)) * 128 + gx) * 256 + c]);
        vs[py][px][cl] = v;
    }
    __syncthreads();

    for (int p = tp; p < 324; p += 16) {
        int py = p / 18, px = p - py * 18;
        float acc = 0.f;
#pragma unroll
        for (int dy = 0; dy < 3; dy++)
#pragma unroll
            for (int dx = 0; dx < 3; dx++)
                acc += vs[py + dy][px + dx][cl] * w1[dy * 3 + dx];
        int gy = ty0 + py - 1, gx = tx0 + px - 1;
        float val = (gy >= 0 && gy < 128 && gx >= 0 && gx < 128) ? gelu_exact(acc) : 0.f;
        t1[py][px][cl] = val;
    }
    __syncthreads();

    for (int p = tp; p < 256; p += 16) {
        int py = p >> 4, px = p & 15;
        float acc = 0.f;
#pragma unroll
        for (int dy = 0; dy < 3; dy++)
#pragma unroll
            for (int dx = 0; dx < 3; dx++)
                acc += t1[py + dy][px + dx][cl] * w2[dy * 3 + dx];
        out[(((size_t)(b * 128 + ty0 + py)) * 128 + tx0 + px) * 256 + c] = acc;
    }
}

extern "C" void kernel_launch(void* const* d_in, const int* in_sizes, int n_in,
                              void* d_out, int out_size)
{
    const float* x_in    = (const float*)d_in[0];
    const float* y_in    = (const float*)d_in[1];
    const float* f_in    = (const float*)d_in[2];
    const float* Wq      = (const float*)d_in[3];
    const float* Wk      = (const float*)d_in[4];
    const float* Wv      = (const float*)d_in[5];
    const float* rescale = (const float*)d_in[6];
    const float* Wp      = (const float*)d_in[7];
    const float* bp      = (const float*)d_in[8];
    const float* pw1     = (const float*)d_in[9];
    const float* pw2     = (const float*)d_in[10];
    float* out = (float*)d_out;

    cudaFuncSetAttribute(k_fused, cudaFuncAttributeMaxDynamicSharedMemorySize, QKG_SMEM);

    // 1) transpose + fp16-convert weights
    k_wt<<<dim3(8, 8, 3), dim3(32, 8)>>>(Wq, Wk, Wv);
    // 2) fused: qkgram (256 blocks) + gemm_v (512 blocks) co-scheduled
    k_fused<<<NQB + 512, 512, QKG_SMEM>>>(x_in, y_in, f_in);
    // 3) softmax + fold attention into Wp -> per-batch Mt (fp16)
    k_attn_m<<<32, 256>>>(Wp, rescale);
    // 4) positional branch writes d_out
    k_conv<<<dim3(64, 16, 4), 256>>>(pw1, pw2, out);
    // 5) out += v @ M[b] + bp (deep pipeline)
    k_gemm_out<<<512, 512>>>(bp, out);
}

// round 14
// speedup vs baseline: 1.6538x; 1.0894x over previous
#include <cuda_runtime.h>
#include <cuda_fp16.h>
#include <math.h>
#include <stdint.h>

#define B_    4
#define NTOK  16384
#define C_    256
#define BN_   65536
#define NQB   256                 // qkgram blocks (256 tokens each)
#define CPB   64                  // chunks per batch = NQB / B_

// ---------------- static device scratch ----------------
__device__ __half g_v[BN_ * C_];
__device__ __half g_Wt[3 * C_ * C_];
__device__ __half g_Mt[B_ * C_ * C_];
__device__ float g_gram_part[NQB * 8 * 32 * 32];   // 8 MB [blk][h][i][j]
__device__ float g_ssq_part[NQB * C_];
__device__ float g_ssk_part[NQB * C_];

__device__ __forceinline__ void mma_f16(float* c, const uint32_t* a, const uint32_t* b) {
    asm volatile(
        "mma.sync.aligned.m16n8k16.row.col.f32.f16.f16.f32 "
        "{%0,%1,%2,%3}, {%4,%5,%6,%7}, {%8,%9}, {%0,%1,%2,%3};"
        : "+f"(c[0]), "+f"(c[1]), "+f"(c[2]), "+f"(c[3])
        : "r"(a[0]), "r"(a[1]), "r"(a[2]), "r"(a[3]), "r"(b[0]), "r"(b[1]));
}
__device__ __forceinline__ void cp16(void* s, const void* g) {
    uint32_t sa = (uint32_t)__cvta_generic_to_shared(s);
    asm volatile("cp.async.cg.shared.global [%0], [%1], 16;" :: "r"(sa), "l"(g));
}
#define CP_COMMIT() asm volatile("cp.async.commit_group;" ::: "memory")
#define CP_WAIT(n)  asm volatile("cp.async.wait_group %0;" :: "n"(n) : "memory")

__device__ __forceinline__ void ldsm4t(uint32_t* r, const __half* p) {
    uint32_t a = (uint32_t)__cvta_generic_to_shared(p);
    asm volatile("ldmatrix.sync.aligned.m8n8.x4.trans.shared.b16 {%0,%1,%2,%3}, [%4];"
                 : "=r"(r[0]), "=r"(r[1]), "=r"(r[2]), "=r"(r[3]) : "r"(a));
}
__device__ __forceinline__ void ldsm2t(uint32_t* r, const __half* p) {
    uint32_t a = (uint32_t)__cvta_generic_to_shared(p);
    asm volatile("ldmatrix.sync.aligned.m8n8.x2.trans.shared.b16 {%0,%1}, [%2];"
                 : "=r"(r[0]), "=r"(r[1]) : "r"(a));
}

#define KC   16
#define SPH  24
#define RS   264

// ---- qkgram smem layout (within dynamic smem) ----
#define KT_OFF  (128 * RS)
#define AH_OFF  (2 * 128 * RS * 2)
#define BH_OFF  (AH_OFF + 2 * 128 * SPH * 2)
#define QKG_SMEM (BH_OFF + 4 * 256 * SPH * 2)    // 196608

// ---- conv/attn merged kernel smem ----
#define CONV_SMEM (51200 + 41472)                // 92672

// projection pass: tile[128x256 fp16 smem] = A[128x256 fp32] @ Bt^T
__device__ __forceinline__ void proj_pass(
    const float* __restrict__ Asrc, const __half* __restrict__ Bt,
    __half* tile, __half* Ah, __half* Bh, int t, float* nacc)
{
    const int warp = t >> 5, lane = t & 31;
    const int wm0 = (warp & 1) * 64, wn0 = (warp >> 1) * 32;
    const int g = lane >> 2, q = lane & 3;
    const int ar = t >> 2, ak4 = (t & 3) * 4;
    const int br = t >> 1, bk = (t & 1) * 8;
    const float* Ab = Asrc + (size_t)ar * 256 + ak4;
    const __half* Bb = Bt + (size_t)br * 256 + bk;

    float acc[4][4][4];
#pragma unroll
    for (int mf = 0; mf < 4; mf++)
#pragma unroll
        for (int nf = 0; nf < 4; nf++)
#pragma unroll
            for (int r = 0; r < 4; r++) acc[mf][nf][r] = 0.f;

    cp16(Bh + 0 * (256 * SPH) + br * SPH + bk, Bb);
    CP_COMMIT();
    cp16(Bh + 1 * (256 * SPH) + br * SPH + bk, Bb + KC);
    CP_COMMIT();
    cp16(Bh + 2 * (256 * SPH) + br * SPH + bk, Bb + 2 * KC);
    CP_COMMIT();
    {
        float4 p0 = *(const float4*)(Ab);
        __half2 h[2];
        h[0] = __float22half2_rn(make_float2(p0.x, p0.y));
        h[1] = __float22half2_rn(make_float2(p0.z, p0.w));
        *(uint2*)&Ah[ar * SPH + ak4] = *(const uint2*)h;
    }
    float4 par0 = *(const float4*)(Ab + KC);
    float4 par1 = *(const float4*)(Ab + 2 * KC);

    for (int c = 0; c < 16; c++) {
        if (c <= 13)      { CP_WAIT(2); }
        else if (c == 14) { CP_WAIT(1); }
        else              { CP_WAIT(0); }
        __syncthreads();
        if (c < 15) {
            __half2 h[2];
            h[0] = __float22half2_rn(make_float2(par0.x, par0.y));
            h[1] = __float22half2_rn(make_float2(par0.z, par0.w));
            *(uint2*)&Ah[((c + 1) & 1) * (128 * SPH) + ar * SPH + ak4] = *(const uint2*)h;
            par0 = par1;
        }
        if (c + 3 < 16) {
            par1 = *(const float4*)(Ab + (c + 3) * KC);
            cp16(Bh + ((c + 3) & 3) * (256 * SPH) + br * SPH + bk, Bb + (c + 3) * KC);
            CP_COMMIT();
        }

        const __half* As = Ah + (c & 1) * (128 * SPH);
        const __half* Bs = Bh + (c & 3) * (256 * SPH);

        uint32_t bf[4][2];
#pragma unroll
        for (int nf = 0; nf < 4; nf++) {
            int n = wn0 + nf * 8 + g;
            bf[nf][0] = *(const uint32_t*)&Bs[n * SPH + 2 * q];
            bf[nf][1] = *(const uint32_t*)&Bs[n * SPH + 2 * q + 8];
        }
#pragma unroll
        for (int mf = 0; mf < 4; mf++) {
            int r = wm0 + mf * 16 + g;
            uint32_t af[4];
            af[0] = *(const uint32_t*)&As[r * SPH + 2 * q];
            af[1] = *(const uint32_t*)&As[(r + 8) * SPH + 2 * q];
            af[2] = *(const uint32_t*)&As[r * SPH + 2 * q + 8];
            af[3] = *(const uint32_t*)&As[(r + 8) * SPH + 2 * q + 8];
#pragma unroll
            for (int nf = 0; nf < 4; nf++)
                mma_f16(acc[mf][nf], af, bf[nf]);
        }
    }

#pragma unroll
    for (int mf = 0; mf < 4; mf++) {
        int r = wm0 + mf * 16 + g;
#pragma unroll
        for (int nf = 0; nf < 4; nf++) {
            int cb = wn0 + nf * 8 + 2 * q;
            __half2 h2a = __float22half2_rn(make_float2(acc[mf][nf][0], acc[mf][nf][1]));
            __half2 h2b = __float22half2_rn(make_float2(acc[mf][nf][2], acc[mf][nf][3]));
            *(__half2*)&tile[r * RS + cb] = h2a;
            *(__half2*)&tile[(r + 8) * RS + cb] = h2b;
            float2 fa = __half22float2(h2a), fb = __half22float2(h2b);
            nacc[nf * 2 + 0] += fa.x * fa.x + fb.x * fb.x;
            nacc[nf * 2 + 1] += fa.y * fa.y + fb.y * fb.y;
        }
    }
}

// ---------------- qkgram body: 256 tokens per block ----------------
__device__ __forceinline__ void qkgram_body(
    char* smem, int blk, const float* __restrict__ x, const float* __restrict__ y)
{
    __half* qtile = (__half*)smem;
    __half* ktile = qtile + KT_OFF;
    __half* Ah = (__half*)(smem + AH_OFF);
    __half* Bh = (__half*)(smem + BH_OFF);

    const size_t tokbase = (size_t)blk * 256;
    const int t = threadIdx.x;
    const int warp = t >> 5, lane = t & 31;

    const int h = warp >> 1, mi = (warp & 1) * 16;
    const int lrowA = (lane & 7) + ((lane >> 4) << 3);
    const int lcolA = ((lane >> 3) & 1) << 3;
    const int lrowB = (lane & 7) + (((lane >> 3) & 1) << 3);
    float gacc[4][4];
#pragma unroll
    for (int nf = 0; nf < 4; nf++)
#pragma unroll
        for (int r = 0; r < 4; r++) gacc[nf][r] = 0.f;

    float nq8[8], nk8[8];
#pragma unroll
    for (int i = 0; i < 8; i++) { nq8[i] = 0.f; nk8[i] = 0.f; }

    for (int s = 0; s < 2; s++) {
        const size_t tb = (tokbase + s * 128) * 256;
        proj_pass(x + tb, g_Wt, qtile, Ah, Bh, t, nq8);
        proj_pass(y + tb, g_Wt + 65536, ktile, Ah, Bh, t, nk8);
        __syncthreads();

#pragma unroll
        for (int k0 = 0; k0 < 128; k0 += 16) {
            uint32_t af[4];
            ldsm4t(af, &ktile[(k0 + lrowA) * RS + h * 32 + mi + lcolA]);
#pragma unroll
            for (int nf = 0; nf < 4; nf++) {
                uint32_t bf[2];
                ldsm2t(bf, &qtile[(k0 + lrowB) * RS + h * 32 + nf * 8]);
                mma_f16(gacc[nf], af, bf);
            }
        }
        __syncthreads();
    }

    {
        const int g2 = lane >> 2, q2 = lane & 3;
        float* gp = g_gram_part + ((size_t)blk * 8 + h) * 1024;
#pragma unroll
        for (int nf = 0; nf < 4; nf++) {
            int cb = nf * 8 + 2 * q2;
            *(float2*)&gp[(mi + g2) * 32 + cb] = make_float2(gacc[nf][0], gacc[nf][1]);
            *(float2*)&gp[(mi + g2 + 8) * 32 + cb] = make_float2(gacc[nf][2], gacc[nf][3]);
        }
    }

#pragma unroll
    for (int i = 0; i < 8; i++) {
#pragma unroll
        for (int off = 4; off <= 16; off <<= 1) {
            nq8[i] += __shfl_xor_sync(0xffffffffu, nq8[i], off);
            nk8[i] += __shfl_xor_sync(0xffffffffu, nk8[i], off);
        }
    }
    float* nsq = (float*)(smem + AH_OFF);
    float* nsk = nsq + 16 * 32;
    if (lane < 4) {
#pragma unroll
        for (int nf = 0; nf < 4; nf++) {
#pragma unroll
            for (int e = 0; e < 2; e++) {
                nsq[warp * 32 + nf * 8 + 2 * lane + e] = nq8[nf * 2 + e];
                nsk[warp * 32 + nf * 8 + 2 * lane + e] = nk8[nf * 2 + e];
            }
        }
    }
    __syncthreads();
    if (t < 256) {
        int j = t >> 5, loc = t & 31;
        g_ssq_part[(size_t)blk * 256 + t] = nsq[(2 * j) * 32 + loc] + nsq[(2 * j + 1) * 32 + loc];
        g_ssk_part[(size_t)blk * 256 + t] = nsk[(2 * j) * 32 + loc] + nsk[(2 * j + 1) * 32 + loc];
    }
}

// ---------------- gemm_v body (deep pipeline, dynamic smem) ----------------
__device__ __forceinline__ void gemmv_body(char* smem, int vblk, const float* __restrict__ f)
{
    __half* Ah = (__half*)smem;
    __half* Bh = (__half*)(smem + 2 * 128 * SPH * 2);

    const __half* Bt = g_Wt + 2 * 65536;
    __half* C = g_v;
    const int row0 = vblk * 128;

    const int t = threadIdx.x;
    const int warp = t >> 5, lane = t & 31;
    const int wm0 = (warp & 1) * 64, wn0 = (warp >> 1) * 32;
    const int g = lane >> 2, q = lane & 3;

    float acc[4][4][4];
#pragma unroll
    for (int mf = 0; mf < 4; mf++)
#pragma unroll
        for (int nf = 0; nf < 4; nf++)
#pragma unroll
            for (int r = 0; r < 4; r++) acc[mf][nf][r] = 0.f;

    const int ar = t >> 2, ak4 = (t & 3) * 4;
    const float* Ab = f + (size_t)(row0 + ar) * 256 + ak4;
    const int br = t >> 1, bk = (t & 1) * 8;
    const __half* Bb = Bt + (size_t)br * 256 + bk;

    cp16(Bh + 0 * (256 * SPH) + br * SPH + bk, Bb);
    CP_COMMIT();
    cp16(Bh + 1 * (256 * SPH) + br * SPH + bk, Bb + KC);
    CP_COMMIT();
    cp16(Bh + 2 * (256 * SPH) + br * SPH + bk, Bb + 2 * KC);
    CP_COMMIT();
    {
        float4 p0 = *(const float4*)(Ab);
        __half2 h[2];
        h[0] = __float22half2_rn(make_float2(p0.x, p0.y));
        h[1] = __float22half2_rn(make_float2(p0.z, p0.w));
        *(uint2*)&Ah[ar * SPH + ak4] = *(const uint2*)h;
    }
    float4 par0 = *(const float4*)(Ab + KC);
    float4 par1 = *(const float4*)(Ab + 2 * KC);

    for (int c = 0; c < 16; c++) {
        if (c <= 13)      { CP_WAIT(2); }
        else if (c == 14) { CP_WAIT(1); }
        else              { CP_WAIT(0); }
        __syncthreads();
        if (c < 15) {
            __half2 h[2];
            h[0] = __float22half2_rn(make_float2(par0.x, par0.y));
            h[1] = __float22half2_rn(make_float2(par0.z, par0.w));
            *(uint2*)&Ah[((c + 1) & 1) * (128 * SPH) + ar * SPH + ak4] = *(const uint2*)h;
            par0 = par1;
        }
        if (c + 3 < 16) {
            par1 = *(const float4*)(Ab + (c + 3) * KC);
            cp16(Bh + ((c + 3) & 3) * (256 * SPH) + br * SPH + bk, Bb + (c + 3) * KC);
            CP_COMMIT();
        }

        const __half* As = Ah + (c & 1) * (128 * SPH);
        const __half* Bs = Bh + (c & 3) * (256 * SPH);

        uint32_t bf[4][2];
#pragma unroll
        for (int nf = 0; nf < 4; nf++) {
            int n = wn0 + nf * 8 + g;
            bf[nf][0] = *(const uint32_t*)&Bs[n * SPH + 2 * q];
            bf[nf][1] = *(const uint32_t*)&Bs[n * SPH + 2 * q + 8];
        }
#pragma unroll
        for (int mf = 0; mf < 4; mf++) {
            int r = wm0 + mf * 16 + g;
            uint32_t af[4];
            af[0] = *(const uint32_t*)&As[r * SPH + 2 * q];
            af[1] = *(const uint32_t*)&As[(r + 8) * SPH + 2 * q];
            af[2] = *(const uint32_t*)&As[r * SPH + 2 * q + 8];
            af[3] = *(const uint32_t*)&As[(r + 8) * SPH + 2 * q + 8];
#pragma unroll
            for (int nf = 0; nf < 4; nf++)
                mma_f16(acc[mf][nf], af, bf[nf]);
        }
    }

#pragma unroll
    for (int mf = 0; mf < 4; mf++) {
        int rbase = row0 + wm0 + mf * 16 + g;
#pragma unroll
        for (int nf = 0; nf < 4; nf++) {
            int cb = wn0 + nf * 8 + 2 * q;
            *(__half2*)(C + (size_t)rbase * 256 + cb)
                = __float22half2_rn(make_float2(acc[mf][nf][0], acc[mf][nf][1]));
            *(__half2*)(C + (size_t)(rbase + 8) * 256 + cb)
                = __float22half2_rn(make_float2(acc[mf][nf][2], acc[mf][nf][3]));
        }
    }
}

// ================= fused launch: qkgram blocks then gemm_v blocks =================
__global__ void __launch_bounds__(512) k_fused(
    const float* __restrict__ x, const float* __restrict__ y, const float* __restrict__ f)
{
    extern __shared__ char smem[];
    if (blockIdx.x < NQB) qkgram_body(smem, blockIdx.x, x, y);
    else                  gemmv_body(smem, blockIdx.x - NQB, f);
}

// ---- OUT: A fp16 + B fp16, both 4-stage cp.async; accumulate into f32 d_out ----
__global__ void __launch_bounds__(512) k_gemm_out(
    const float* __restrict__ bp, float* __restrict__ out)
{
    __shared__ __half As4[4][128 * SPH];
    __shared__ __half Bs4[4][256 * SPH];

    const int row0 = blockIdx.x * 128;
    const int b = row0 >> 14;
    const __half* Bt = g_Mt + (size_t)b * 65536;

    const int t = threadIdx.x;
    const int warp = t >> 5, lane = t & 31;
    const int wm0 = (warp & 1) * 64, wn0 = (warp >> 1) * 32;
    const int g = lane >> 2, q = lane & 3;

    float acc[4][4][4];
#pragma unroll
    for (int mf = 0; mf < 4; mf++)
#pragma unroll
        for (int nf = 0; nf < 4; nf++)
#pragma unroll
            for (int r = 0; r < 4; r++) acc[mf][nf][r] = 0.f;

    const int ar = t >> 1, ak = (t & 1) * 8;
    const __half* Ab = g_v + (size_t)(row0 + ar) * 256 + ak;
    const __half* Bb = Bt + (size_t)ar * 256 + ak;

#pragma unroll
    for (int pc = 0; pc < 3; pc++) {
        if (t < 256) cp16(&As4[pc][ar * SPH + ak], Ab + pc * KC);
        cp16(&Bs4[pc][ar * SPH + ak], Bb + pc * KC);
        CP_COMMIT();
    }

    for (int c = 0; c < 16; c++) {
        if (c <= 13)      { CP_WAIT(2); }
        else if (c == 14) { CP_WAIT(1); }
        else              { CP_WAIT(0); }
        __syncthreads();
        if (c + 3 < 16) {
            if (t < 256) cp16(&As4[(c + 3) & 3][ar * SPH + ak], Ab + (c + 3) * KC);
            cp16(&Bs4[(c + 3) & 3][ar * SPH + ak], Bb + (c + 3) * KC);
            CP_COMMIT();
        }
        const __half* As = As4[c & 3];
        const __half* Bs = Bs4[c & 3];

        uint32_t bf[4][2];
#pragma unroll
        for (int nf = 0; nf < 4; nf++) {
            int n = wn0 + nf * 8 + g;
            bf[nf][0] = *(const uint32_t*)&Bs[n * SPH + 2 * q];
            bf[nf][1] = *(const uint32_t*)&Bs[n * SPH + 2 * q + 8];
        }
#pragma unroll
        for (int mf = 0; mf < 4; mf++) {
            int r = wm0 + mf * 16 + g;
            uint32_t af[4];
            af[0] = *(const uint32_t*)&As[r * SPH + 2 * q];
            af[1] = *(const uint32_t*)&As[(r + 8) * SPH + 2 * q];
            af[2] = *(const uint32_t*)&As[r * SPH + 2 * q + 8];
            af[3] = *(const uint32_t*)&As[(r + 8) * SPH + 2 * q + 8];
#pragma unroll
            for (int nf = 0; nf < 4; nf++)
                mma_f16(acc[mf][nf], af, bf[nf]);
        }
    }

#pragma unroll
    for (int mf = 0; mf < 4; mf++) {
        int rbase = row0 + wm0 + mf * 16 + g;
#pragma unroll
        for (int nf = 0; nf < 4; nf++) {
            int cb = wn0 + nf * 8 + 2 * q;
            float2 bb = *(const float2*)(bp + cb);
            float2* p0 = (float2*)(out + (size_t)rbase * 256 + cb);
            float2* p1 = (float2*)(out + (size_t)(rbase + 8) * 256 + cb);
            float2 o0 = *p0, o1 = *p1;
            o0.x += acc[mf][nf][0] + bb.x; o0.y += acc[mf][nf][1] + bb.y;
            o1.x += acc[mf][nf][2] + bb.x; o1.y += acc[mf][nf][3] + bb.y;
            *p0 = o0;
            *p1 = o1;
        }
    }
}

// =================== weight transpose + fp16 conversion ===================
__global__ void k_wt(const float* __restrict__ Wq, const float* __restrict__ Wk,
                     const float* __restrict__ Wv)
{
    int z = blockIdx.z;
    const float* W = (z == 0) ? Wq : (z == 1) ? Wk : Wv;
    __half* Wt = g_Wt + (size_t)z * 65536;
    __shared__ float tile[32][33];
    int tx = threadIdx.x, ty = threadIdx.y;
    int k0 = blockIdx.y * 32, n0 = blockIdx.x * 32;
#pragma unroll
    for (int i = 0; i < 4; i++)
        tile[ty + 8 * i][tx] = W[(size_t)(k0 + ty + 8 * i) * 256 + n0 + tx];
    __syncthreads();
#pragma unroll
    for (int i = 0; i < 4; i++)
        Wt[(size_t)(n0 + ty + 8 * i) * 256 + k0 + tx] = __float2half_rn(tile[tx][ty + 8 * i]);
}

__device__ __forceinline__ float gelu_exact(float x)
{
    return 0.5f * x * (1.0f + erff(x * 0.7071067811865475f));
}

// ============ attn_m body (unchanged math) ============
__device__ __forceinline__ void attn_body(
    char* smem, int bh, const float* __restrict__ Wp, const float* __restrict__ rescale)
{
    int b = bh >> 3, h = bh & 7;
    int t = threadIdx.x;
    float* attn = (float*)smem;                    // [32][32]
    float* wp = (float*)(smem + 4096);             // [32][256]
    float* nq = (float*)(smem + 4096 + 32768);     // [32]
    float* nk = nq + 32;

#pragma unroll
    for (int s = 0; s < 32; s++) {
        int idx = t + s * 256;
        wp[(idx >> 8) * 256 + (idx & 255)] = Wp[(size_t)(h * 32 + (idx >> 8)) * 256 + (idx & 255)];
    }
    if (t < 32) {
        float sq = 0.f, sk = 0.f;
#pragma unroll
        for (int ch = 0; ch < CPB; ch++) {
            sq += g_ssq_part[(size_t)(b * CPB + ch) * 256 + h * 32 + t];
            sk += g_ssk_part[(size_t)(b * CPB + ch) * 256 + h * 32 + t];
        }
        nq[t] = fmaxf(sqrtf(sq), 1e-12f);
        nk[t] = fmaxf(sqrtf(sk), 1e-12f);
    }
    __syncthreads();

    float resc = rescale[h];
    int w = t >> 5, lane = t & 31;
    for (int i = w; i < 32; i += 8) {
        float g = 0.f;
#pragma unroll
        for (int ch = 0; ch < CPB; ch++)
            g += g_gram_part[((size_t)(b * CPB + ch) * 8 + h) * 1024 + i * 32 + lane];
        float val = g / (nk[i] * nq[lane]) * resc;
        float m = val;
#pragma unroll
        for (int o = 16; o; o >>= 1) m = fmaxf(m, __shfl_xor_sync(0xffffffffu, m, o));
        float e = expf(val - m);
        float ssum = e;
#pragma unroll
        for (int o = 16; o; o >>= 1) ssum += __shfl_xor_sync(0xffffffffu, ssum, o);
        attn[i * 32 + lane] = e / ssum;
    }
    __syncthreads();

    float acc[32];
#pragma unroll
    for (int j = 0; j < 32; j++) acc[j] = 0.f;
#pragma unroll 4
    for (int i = 0; i < 32; i++) {
        float wpv = wp[i * 256 + t];
#pragma unroll
        for (int j = 0; j < 32; j++) acc[j] += attn[i * 32 + j] * wpv;
    }
#pragma unroll
    for (int j = 0; j < 32; j++)
        g_Mt[((size_t)b * 256 + t) * 256 + h * 32 + j] = __float2half_rn(acc[j]);
}

// ============ conv body: 16x16 px, 32 ch (float2 per thread) ============
__device__ __forceinline__ void conv_body(
    char* smem, int cid, const float* __restrict__ pw1, const float* __restrict__ pw2,
    float* __restrict__ out)
{
    float2* vs = (float2*)smem;                    // [20][20][16]
    float2* t1 = (float2*)(smem + 51200);          // [18][18][16]

    const int t = threadIdx.x;
    const int cl = t & 15;
    const int tp = t >> 4;
    const int b = cid >> 9;
    const int rem = cid & 511;
    const int chk = rem >> 6;                      // 0..7
    const int tile = rem & 63;
    const int c0 = chk * 32 + 2 * cl;
    const int tx0 = (tile & 7) * 16, ty0 = (tile >> 3) * 16;

    float2 w1[9], w2[9];
#pragma unroll
    for (int i = 0; i < 9; i++) {
        w1[i] = *(const float2*)(pw1 + i * 256 + c0);
        w2[i] = *(const float2*)(pw2 + i * 256 + c0);
    }

    for (int p = tp; p < 400; p += 16) {
        int py = p / 20, px = p - py * 20;
        int gy = ty0 + py - 2, gx = tx0 + px - 2;
        float2 v = make_float2(0.f, 0.f);
        if (gy >= 0 && gy < 128 && gx >= 0 && gx < 128) {
            __half2 hv = *(const __half2*)(g_v + (((size_t)(b * 128 + gy)) * 128 + gx) * 256 + c0);
            v = __half22float2(hv);
        }
        vs[(py * 20 + px) * 16 + cl] = v;
    }
    __syncthreads();

    for (int p = tp; p < 324; p += 16) {
        int py = p / 18, px = p - py * 18;
        float2 acc = make_float2(0.f, 0.f);
#pragma unroll
        for (int dy = 0; dy < 3; dy++)
#pragma unroll
            for (int dx = 0; dx < 3; dx++) {
                float2 vv = vs[((py + dy) * 20 + px + dx) * 16 + cl];
                float2 ww = w1[dy * 3 + dx];
                acc.x += vv.x * ww.x;
                acc.y += vv.y * ww.y;
            }
        int gy = ty0 + py - 1, gx = tx0 + px - 1;
        float2 val = make_float2(0.f, 0.f);
        if (gy >= 0 && gy < 128 && gx >= 0 && gx < 128) {
            val.x = gelu_exact(acc.x);
            val.y = gelu_exact(acc.y);
        }
        t1[(py * 18 + px) * 16 + cl] = val;
    }
    __syncthreads();

    for (int p = tp; p < 256; p += 16) {
        int py = p >> 4, px = p & 15;
        float2 acc = make_float2(0.f, 0.f);
#pragma unroll
        for (int dy = 0; dy < 3; dy++)
#pragma unroll
            for (int dx = 0; dx < 3; dx++) {
                float2 vv = t1[((py + dy) * 18 + px + dx) * 16 + cl];
                float2 ww = w2[dy * 3 + dx];
                acc.x += vv.x * ww.x;
                acc.y += vv.y * ww.y;
            }
        *(float2*)(out + (((size_t)(b * 128 + ty0 + py)) * 128 + tx0 + px) * 256 + c0) = acc;
    }
}

// ============ merged conv + attn_m launch ============
__global__ void __launch_bounds__(256) k_conv_attn(
    const float* __restrict__ Wp, const float* __restrict__ rescale,
    const float* __restrict__ pw1, const float* __restrict__ pw2,
    float* __restrict__ out)
{
    extern __shared__ char smem[];
    if (blockIdx.x < 32) attn_body(smem, blockIdx.x, Wp, rescale);
    else                 conv_body(smem, blockIdx.x - 32, pw1, pw2, out);
}

extern "C" void kernel_launch(void* const* d_in, const int* in_sizes, int n_in,
                              void* d_out, int out_size)
{
    const float* x_in    = (const float*)d_in[0];
    const float* y_in    = (const float*)d_in[1];
    const float* f_in    = (const float*)d_in[2];
    const float* Wq      = (const float*)d_in[3];
    const float* Wk      = (const float*)d_in[4];
    const float* Wv      = (const float*)d_in[5];
    const float* rescale = (const float*)d_in[6];
    const float* Wp      = (const float*)d_in[7];
    const float* bp      = (const float*)d_in[8];
    const float* pw1     = (const float*)d_in[9];
    const float* pw2     = (const float*)d_in[10];
    float* out = (float*)d_out;

    cudaFuncSetAttribute(k_fused, cudaFuncAttributeMaxDynamicSharedMemorySize, QKG_SMEM);
    cudaFuncSetAttribute(k_conv_attn, cudaFuncAttributeMaxDynamicSharedMemorySize, CONV_SMEM);

    // 1) transpose + fp16-convert weights
    k_wt<<<dim3(8, 8, 3), dim3(32, 8)>>>(Wq, Wk, Wv);
    // 2) fused: qkgram (256 blocks) + gemm_v (512 blocks)
    k_fused<<<NQB + 512, 512, QKG_SMEM>>>(x_in, y_in, f_in);
    // 3) merged: attn_m (32 blocks) + conv float2 (2048 blocks); conv writes d_out
    k_conv_attn<<<32 + 2048, 256, CONV_SMEM>>>(Wp, rescale, pw1, pw2, out);
    // 4) out += v @ M[b] + bp (deep pipeline)
    k_gemm_out<<<512, 512>>>(bp, out);
}